// round 1
// baseline (speedup 1.0000x reference)
#include <cuda_runtime.h>
#include <cuda_bf16.h>
#include <cstdint>

// Problem constants
#define BB   2
#define SS   2048
#define DD   1024
#define HH   16
#define HDIM 64
#define MROWS (BB*SS)      // 4096

// ---------------- scratch (no allocations allowed) ----------------
__device__ float g_q[MROWS * DD];
__device__ float g_k[MROWS * DD];
__device__ float g_v[MROWS * DD];
__device__ float g_a[MROWS * DD];

// ---------------- fp32 tiled GEMM: C = A(MxK) @ B(KxN) + bias ----------------
#define GBM 128
#define GBN 128
#define GBK 8
#define GTM 8
#define GTN 8

__global__ __launch_bounds__(256, 2)
void gemm_bias_kernel(const float* __restrict__ A, const float* __restrict__ B,
                      const float* __restrict__ bias, float* __restrict__ C,
                      int M, int N, int K)
{
    __shared__ float As[GBK][GBM];
    __shared__ float Bs[GBK][GBN];

    const int tid  = threadIdx.x;
    const int brow = blockIdx.y;
    const int bcol = blockIdx.x;

    const int arow = tid >> 1;          // 0..127
    const int acol = (tid & 1) << 2;    // 0 or 4
    const int brl  = tid >> 5;          // 0..7
    const int bcl  = (tid & 31) << 2;   // 0..124

    const int trow = (tid >> 4) << 3;   // 0..120
    const int tcol = (tid & 15) << 3;   // 0..120

    const float* Ablk = A + (size_t)brow * GBM * K;
    const float* Bblk = B + bcol * GBN;

    float acc[GTM][GTN];
    #pragma unroll
    for (int i = 0; i < GTM; i++)
        #pragma unroll
        for (int j = 0; j < GTN; j++) acc[i][j] = 0.f;

    for (int k0 = 0; k0 < K; k0 += GBK) {
        float4 av = *(const float4*)(Ablk + (size_t)arow * K + k0 + acol);
        As[acol + 0][arow] = av.x;
        As[acol + 1][arow] = av.y;
        As[acol + 2][arow] = av.z;
        As[acol + 3][arow] = av.w;
        *(float4*)&Bs[brl][bcl] = *(const float4*)(Bblk + (size_t)(k0 + brl) * N + bcl);
        __syncthreads();

        #pragma unroll
        for (int k = 0; k < GBK; k++) {
            float ra[GTM], rb[GTN];
            *(float4*)&ra[0] = *(const float4*)&As[k][trow];
            *(float4*)&ra[4] = *(const float4*)&As[k][trow + 4];
            *(float4*)&rb[0] = *(const float4*)&Bs[k][tcol];
            *(float4*)&rb[4] = *(const float4*)&Bs[k][tcol + 4];
            #pragma unroll
            for (int i = 0; i < GTM; i++)
                #pragma unroll
                for (int j = 0; j < GTN; j++)
                    acc[i][j] = fmaf(ra[i], rb[j], acc[i][j]);
        }
        __syncthreads();
    }

    float* Cblk = C + (size_t)brow * GBM * N + bcol * GBN;
    float bi[GTN];
    *(float4*)&bi[0] = *(const float4*)(bias + bcol * GBN + tcol);
    *(float4*)&bi[4] = *(const float4*)(bias + bcol * GBN + tcol + 4);
    #pragma unroll
    for (int i = 0; i < GTM; i++) {
        float4 r0 = make_float4(acc[i][0] + bi[0], acc[i][1] + bi[1],
                                acc[i][2] + bi[2], acc[i][3] + bi[3]);
        float4 r1 = make_float4(acc[i][4] + bi[4], acc[i][5] + bi[5],
                                acc[i][6] + bi[6], acc[i][7] + bi[7]);
        *(float4*)(Cblk + (size_t)(trow + i) * N + tcol)     = r0;
        *(float4*)(Cblk + (size_t)(trow + i) * N + tcol + 4) = r1;
    }
}

// ---------------- flash attention (fp32, causal) ----------------
// BR=128 query rows, BC=64 keys per tile. 256 threads, 8x4 per-thread tile.
// smem: Qs[k][r] stride 132, KPs (K^T then P) stride 132, Vs[c][d] stride 68.
#define FSTRIDE 132
#define VSTRIDE 68
#define FSMEM_FLOATS (2 * 64 * FSTRIDE + 64 * VSTRIDE)
#define FSMEM_BYTES  (FSMEM_FLOATS * 4)

__global__ __launch_bounds__(256, 2)
void flash_kernel(const float* __restrict__ Qg, const float* __restrict__ Kg,
                  const float* __restrict__ Vg, float* __restrict__ Og)
{
    extern __shared__ float sm[];
    float* Qs  = sm;                    // [64 k][128 r] stride 132
    float* KPs = sm + 64 * FSTRIDE;     // K^T [64 k][64 c], later P [64 c][128 r]
    float* Vs  = sm + 2 * 64 * FSTRIDE; // [64 c][64 d] stride 68

    const int qt  = (gridDim.x - 1) - blockIdx.x;  // heavy blocks first
    const int h   = blockIdx.y;
    const int b   = blockIdx.z;
    const int tid = threadIdx.x;
    const size_t hbase = ((size_t)b * SS) * DD + h * HDIM;

    // Load Q tile (128 x 64), transposed into Qs, pre-scaled by 1/sqrt(HD)=0.125
    {
        const int lr = tid >> 1;              // 0..127
        const int lc = (tid & 1) * 32;        // 0 or 32
        const float* qp = Qg + hbase + (size_t)(qt * 128 + lr) * DD + lc;
        #pragma unroll
        for (int v = 0; v < 8; v++) {
            float4 x = *(const float4*)(qp + v * 4);
            const int k = lc + v * 4;
            Qs[(k + 0) * FSTRIDE + lr] = x.x * 0.125f;
            Qs[(k + 1) * FSTRIDE + lr] = x.y * 0.125f;
            Qs[(k + 2) * FSTRIDE + lr] = x.z * 0.125f;
            Qs[(k + 3) * FSTRIDE + lr] = x.w * 0.125f;
        }
    }

    const int tr = (tid >> 4) << 3;   // row base 0..120
    const int tc = (tid & 15) << 2;   // col base 0..60

    float m[8], l[8], o[8][4];
    #pragma unroll
    for (int i = 0; i < 8; i++) {
        m[i] = -1e30f; l[i] = 0.f;
        #pragma unroll
        for (int j = 0; j < 4; j++) o[i][j] = 0.f;
    }

    const int nkt = 2 * qt + 2;
    const int lr = tid >> 2;             // key loader row 0..63
    const int lc = (tid & 3) * 16;

    for (int kt = 0; kt < nkt; kt++) {
        __syncthreads();  // prev-iter P/V reads done; first iter covers Q load
        {
            const float* kp = Kg + hbase + (size_t)(kt * 64 + lr) * DD + lc;
            #pragma unroll
            for (int v = 0; v < 4; v++) {
                float4 x = *(const float4*)(kp + v * 4);
                const int k = lc + v * 4;
                KPs[(k + 0) * FSTRIDE + lr] = x.x;
                KPs[(k + 1) * FSTRIDE + lr] = x.y;
                KPs[(k + 2) * FSTRIDE + lr] = x.z;
                KPs[(k + 3) * FSTRIDE + lr] = x.w;
            }
            const float* vp = Vg + hbase + (size_t)(kt * 64 + lr) * DD + lc;
            #pragma unroll
            for (int v = 0; v < 4; v++)
                *(float4*)&Vs[lr * VSTRIDE + lc + v * 4] = *(const float4*)(vp + v * 4);
        }
        __syncthreads();

        // scores S = Q K^T (pre-scaled)
        float s[8][4];
        #pragma unroll
        for (int i = 0; i < 8; i++)
            #pragma unroll
            for (int j = 0; j < 4; j++) s[i][j] = 0.f;

        #pragma unroll 4
        for (int k = 0; k < 64; k++) {
            float a[8], bb[4];
            *(float4*)&a[0] = *(const float4*)&Qs[k * FSTRIDE + tr];
            *(float4*)&a[4] = *(const float4*)&Qs[k * FSTRIDE + tr + 4];
            *(float4*)&bb[0] = *(const float4*)&KPs[k * FSTRIDE + tc];
            #pragma unroll
            for (int i = 0; i < 8; i++)
                #pragma unroll
                for (int j = 0; j < 4; j++)
                    s[i][j] = fmaf(a[i], bb[j], s[i][j]);
        }

        // causal mask on the two diagonal-adjacent tiles
        if (kt >= 2 * qt) {
            const int off = (kt - 2 * qt) * 64;  // 0 or 64
            #pragma unroll
            for (int i = 0; i < 8; i++)
                #pragma unroll
                for (int j = 0; j < 4; j++)
                    if (off + tc + j > tr + i) s[i][j] = -1e30f;
        }

        // online softmax (row stats across 16 lanes)
        #pragma unroll
        for (int i = 0; i < 8; i++) {
            float mt = fmaxf(fmaxf(s[i][0], s[i][1]), fmaxf(s[i][2], s[i][3]));
            mt = fmaxf(mt, __shfl_xor_sync(0xffffffffu, mt, 1));
            mt = fmaxf(mt, __shfl_xor_sync(0xffffffffu, mt, 2));
            mt = fmaxf(mt, __shfl_xor_sync(0xffffffffu, mt, 4));
            mt = fmaxf(mt, __shfl_xor_sync(0xffffffffu, mt, 8));
            const float mn = fmaxf(m[i], mt);
            const float alpha = __expf(m[i] - mn);
            m[i] = mn;
            float ls = 0.f;
            #pragma unroll
            for (int j = 0; j < 4; j++) {
                const float p = __expf(s[i][j] - mn);
                s[i][j] = p;
                ls += p;
            }
            ls += __shfl_xor_sync(0xffffffffu, ls, 1);
            ls += __shfl_xor_sync(0xffffffffu, ls, 2);
            ls += __shfl_xor_sync(0xffffffffu, ls, 4);
            ls += __shfl_xor_sync(0xffffffffu, ls, 8);
            l[i] = l[i] * alpha + ls;
            #pragma unroll
            for (int j = 0; j < 4; j++) o[i][j] *= alpha;
        }

        __syncthreads();  // all K^T reads done before P overwrite
        #pragma unroll
        for (int j = 0; j < 4; j++) {
            *(float4*)&KPs[(tc + j) * FSTRIDE + tr] =
                make_float4(s[0][j], s[1][j], s[2][j], s[3][j]);
            *(float4*)&KPs[(tc + j) * FSTRIDE + tr + 4] =
                make_float4(s[4][j], s[5][j], s[6][j], s[7][j]);
        }
        __syncthreads();

        // O += P @ V
        #pragma unroll 4
        for (int c = 0; c < 64; c++) {
            float a[8], vv[4];
            *(float4*)&a[0] = *(const float4*)&KPs[c * FSTRIDE + tr];
            *(float4*)&a[4] = *(const float4*)&KPs[c * FSTRIDE + tr + 4];
            *(float4*)&vv[0] = *(const float4*)&Vs[c * VSTRIDE + tc];
            #pragma unroll
            for (int i = 0; i < 8; i++)
                #pragma unroll
                for (int j = 0; j < 4; j++)
                    o[i][j] = fmaf(a[i], vv[j], o[i][j]);
        }
    }

    // epilogue: normalize and store to (b, s, h*64 + d) layout
    #pragma unroll
    for (int i = 0; i < 8; i++) {
        const float inv = 1.0f / l[i];
        float4 r = make_float4(o[i][0] * inv, o[i][1] * inv, o[i][2] * inv, o[i][3] * inv);
        *(float4*)(Og + hbase + (size_t)(qt * 128 + tr + i) * DD + tc) = r;
    }
}

// ---------------- launch ----------------
extern "C" void kernel_launch(void* const* d_in, const int* in_sizes, int n_in,
                              void* d_out, int out_size)
{
    const float* queries = (const float*)d_in[0];
    const float* keys    = (const float*)d_in[1];
    // d_in[2] values: dead (reference projects V from projected K)
    // d_in[3] mask: causal tril, implemented analytically
    const float* Wq = (const float*)d_in[4];
    const float* bq = (const float*)d_in[5];
    const float* Wk = (const float*)d_in[6];
    const float* bk = (const float*)d_in[7];
    const float* Wv = (const float*)d_in[8];
    const float* bv = (const float*)d_in[9];
    const float* Wo = (const float*)d_in[10];
    const float* bo = (const float*)d_in[11];
    float* out = (float*)d_out;

    float *q, *k, *v, *a;
    cudaGetSymbolAddress((void**)&q, g_q);
    cudaGetSymbolAddress((void**)&k, g_k);
    cudaGetSymbolAddress((void**)&v, g_v);
    cudaGetSymbolAddress((void**)&a, g_a);

    static bool attr_set = false;
    (void)attr_set;
    cudaFuncSetAttribute(flash_kernel, cudaFuncAttributeMaxDynamicSharedMemorySize,
                         FSMEM_BYTES);

    dim3 gblk(256);
    dim3 ggrid(DD / GBN, MROWS / GBM);   // (8, 32)

    gemm_bias_kernel<<<ggrid, gblk>>>(queries, Wq, bq, q, MROWS, DD, DD);
    gemm_bias_kernel<<<ggrid, gblk>>>(keys,    Wk, bk, k, MROWS, DD, DD);
    gemm_bias_kernel<<<ggrid, gblk>>>(k,       Wv, bv, v, MROWS, DD, DD);

    dim3 fgrid(SS / 128, HH, BB);        // (16, 16, 2)
    flash_kernel<<<fgrid, dim3(256), FSMEM_BYTES>>>(q, k, v, a);

    gemm_bias_kernel<<<ggrid, gblk>>>(a, Wo, bo, out, MROWS, DD, DD);
}

// round 3
// speedup vs baseline: 1.3865x; 1.3865x over previous
#include <cuda_runtime.h>
#include <cuda_bf16.h>
#include <cstdint>

// Problem constants
#define BB   2
#define SS   2048
#define DD   1024
#define HH   16
#define HDIM 64
#define MROWS (BB*SS)      // 4096

// ---------------- scratch (no allocations allowed) ----------------
__device__ float g_q[MROWS * DD];
__device__ float g_k[MROWS * DD];
__device__ float g_v[MROWS * DD];
__device__ float g_a[MROWS * DD];

// ============================================================================
// mma.sync helpers (baseline PTX — works with plain sm_103 target)
// ============================================================================
__device__ __forceinline__ uint32_t smem_u32(const void* p) {
    uint32_t a;
    asm("{ .reg .u64 t; cvta.to.shared.u64 t, %1; cvt.u32.u64 %0, t; }"
        : "=r"(a) : "l"(p));
    return a;
}

__device__ __forceinline__ void ldsm4(uint32_t* r, uint32_t addr) {
    asm volatile("ldmatrix.sync.aligned.m8n8.x4.shared.b16 {%0,%1,%2,%3}, [%4];"
                 : "=r"(r[0]), "=r"(r[1]), "=r"(r[2]), "=r"(r[3]) : "r"(addr));
}

__device__ __forceinline__ void mma16816(float* c, const uint32_t* a,
                                         uint32_t b0, uint32_t b1) {
    asm volatile(
        "mma.sync.aligned.m16n8k16.row.col.f32.bf16.bf16.f32 "
        "{%0,%1,%2,%3}, {%4,%5,%6,%7}, {%8,%9}, {%0,%1,%2,%3};"
        : "+f"(c[0]), "+f"(c[1]), "+f"(c[2]), "+f"(c[3])
        : "r"(a[0]), "r"(a[1]), "r"(a[2]), "r"(a[3]), "r"(b0), "r"(b1));
}

__device__ __forceinline__ void split8(const float* v, uint4& hi, uint4& lo) {
    uint32_t h[8], l[8];
    #pragma unroll
    for (int i = 0; i < 8; i++) {
        __nv_bfloat16 bh = __float2bfloat16(v[i]);
        float r = v[i] - __bfloat162float(bh);
        __nv_bfloat16 bl = __float2bfloat16(r);
        h[i] = (uint32_t)__bfloat16_as_ushort(bh);
        l[i] = (uint32_t)__bfloat16_as_ushort(bl);
    }
    hi = make_uint4(h[0] | (h[1] << 16), h[2] | (h[3] << 16),
                    h[4] | (h[5] << 16), h[6] | (h[7] << 16));
    lo = make_uint4(l[0] | (l[1] << 16), l[2] | (l[3] << 16),
                    l[4] | (l[5] << 16), l[6] | (l[7] << 16));
}

// ============================================================================
// bf16-split tensor-core GEMM: C[4096,1024] = A @ W + bias (fp32 in/out)
// CTA tile 128x128, K-chunk 64. 3 passes: Ahi*Bhi + Ahi*Blo + Alo*Bhi.
// smem: padded K-major tiles, stride 72 bf16 (144 B) -> conflict-free ldmatrix.
// ============================================================================
#define TCH   64                   // K chunk
#define TSTR  72                   // smem row stride in bf16
#define TILE_BYTES (128 * TSTR * 2)   // 18432
#define SM_AHI 0
#define SM_ALO (SM_AHI + TILE_BYTES)
#define SM_BHI (SM_ALO + TILE_BYTES)
#define SM_BLO (SM_BHI + TILE_BYTES)
#define TC_SMEM (SM_BLO + TILE_BYTES)  // 73728

__global__ __launch_bounds__(256, 2)
void tc_gemm_kernel(const float* __restrict__ A, const float* __restrict__ W,
                    const float* __restrict__ bias, float* __restrict__ C)
{
    extern __shared__ char smem[];
    const uint32_t sb = smem_u32(smem);
    const int tid  = threadIdx.x;
    const int wid  = tid >> 5;
    const int lane = tid & 31;
    const int bn = blockIdx.x;
    const int bm = blockIdx.y;

    // warp grid 4(m) x 2(n): warp tile 32(m) x 64(n)
    const int mw = wid >> 1;        // 0..3
    const int nw = wid & 1;         // 0..1

    // loader indices
    const int ar  = tid >> 1;              // A row 0..127
    const int akh = (tid & 1) * 32;        // A k-half
    const int bnl = tid & 127;             // B n-row 0..127
    const int bkh = (tid >> 7) * 32;       // B k-half

    const float* Ap = A + (size_t)(bm * 128 + ar) * DD + akh;
    const float* Wp = W + (size_t)bkh * DD + bn * 128 + bnl;

    // ldmatrix per-lane addressing: row = lane%16, koff = (lane/16)*8
    const int lrow = lane & 15;
    const int lkof = (lane >> 4) << 3;

    const uint32_t aAddr0 = sb + (uint32_t)(((mw * 32 + lrow) * TSTR + lkof) * 2);
    const uint32_t aAddr1 = aAddr0 + 16 * TSTR * 2;
    const uint32_t bAddr  = sb + (uint32_t)(((nw * 64 + lrow) * TSTR + lkof) * 2);

    float acc[2][8][4];
    #pragma unroll
    for (int i = 0; i < 2; i++)
        #pragma unroll
        for (int j = 0; j < 8; j++)
            #pragma unroll
            for (int q = 0; q < 4; q++) acc[i][j][q] = 0.f;

    for (int c = 0; c < DD / TCH; c++) {
        if (c) __syncthreads();
        // ---- A tile: 128 x 64, fp32 -> bf16 hi/lo ----
        #pragma unroll
        for (int g = 0; g < 4; g++) {
            float v[8];
            *(float4*)&v[0] = *(const float4*)(Ap + c * TCH + g * 8);
            *(float4*)&v[4] = *(const float4*)(Ap + c * TCH + g * 8 + 4);
            uint4 hi, lo;
            split8(v, hi, lo);
            const uint32_t off = (uint32_t)((ar * TSTR + akh + g * 8) * 2);
            *(uint4*)(smem + SM_AHI + off) = hi;
            *(uint4*)(smem + SM_ALO + off) = lo;
        }
        // ---- B tile: W[k][n] -> smem [n][k] (coalesced global reads) ----
        #pragma unroll
        for (int g = 0; g < 4; g++) {
            float v[8];
            #pragma unroll
            for (int i = 0; i < 8; i++)
                v[i] = Wp[(size_t)(c * TCH + g * 8 + i) * DD];
            uint4 hi, lo;
            split8(v, hi, lo);
            const uint32_t off = (uint32_t)((bnl * TSTR + bkh + g * 8) * 2);
            *(uint4*)(smem + SM_BHI + off) = hi;
            *(uint4*)(smem + SM_BLO + off) = lo;
        }
        __syncthreads();

        #pragma unroll
        for (int ks = 0; ks < TCH / 16; ks++) {
            const uint32_t kb = ks * 32;  // 16 bf16 = 32 bytes
            uint32_t ahi[2][4], alo[2][4];
            ldsm4(ahi[0], aAddr0 + SM_AHI + kb);
            ldsm4(ahi[1], aAddr1 + SM_AHI + kb);
            ldsm4(alo[0], aAddr0 + SM_ALO + kb);
            ldsm4(alo[1], aAddr1 + SM_ALO + kb);
            #pragma unroll
            for (int np = 0; np < 4; np++) {   // n-tile pairs (16 n each)
                uint32_t bhi[4], blo[4];
                const uint32_t bofs = (uint32_t)(np * 16 * TSTR * 2) + kb;
                ldsm4(bhi, bAddr + SM_BHI + bofs);
                ldsm4(blo, bAddr + SM_BLO + bofs);
                #pragma unroll
                for (int half = 0; half < 2; half++) {
                    const uint32_t bh0 = bhi[half], bh1 = bhi[half + 2];
                    const uint32_t bl0 = blo[half], bl1 = blo[half + 2];
                    #pragma unroll
                    for (int mi = 0; mi < 2; mi++) {
                        float* cc = acc[mi][np * 2 + half];
                        mma16816(cc, ahi[mi], bh0, bh1);
                        mma16816(cc, ahi[mi], bl0, bl1);
                        mma16816(cc, alo[mi], bh0, bh1);
                    }
                }
            }
        }
    }

    // ---- epilogue: registers -> C with bias ----
    const int tg = lane >> 2;        // 0..7
    const int tq = lane & 3;         // 0..3
    #pragma unroll
    for (int mi = 0; mi < 2; mi++) {
        const int gr0 = bm * 128 + mw * 32 + mi * 16 + tg;
        #pragma unroll
        for (int nj = 0; nj < 8; nj++) {
            const int gc = bn * 128 + nw * 64 + nj * 8 + tq * 2;
            const float b0 = bias[gc], b1 = bias[gc + 1];
            float* c0 = &acc[mi][nj][0];
            *(float2*)(C + (size_t)gr0 * DD + gc) =
                make_float2(c0[0] + b0, c0[1] + b1);
            *(float2*)(C + (size_t)(gr0 + 8) * DD + gc) =
                make_float2(c0[2] + b0, c0[3] + b1);
        }
    }
}

// ---------------- flash attention (fp32, causal) — unchanged ----------------
#define FSTRIDE 132
#define VSTRIDE 68
#define FSMEM_FLOATS (2 * 64 * FSTRIDE + 64 * VSTRIDE)
#define FSMEM_BYTES  (FSMEM_FLOATS * 4)

__global__ __launch_bounds__(256, 2)
void flash_kernel(const float* __restrict__ Qg, const float* __restrict__ Kg,
                  const float* __restrict__ Vg, float* __restrict__ Og)
{
    extern __shared__ float sm[];
    float* Qs  = sm;                    // [64 k][128 r] stride 132
    float* KPs = sm + 64 * FSTRIDE;     // K^T [64 k][64 c], later P [64 c][128 r]
    float* Vs  = sm + 2 * 64 * FSTRIDE; // [64 c][64 d] stride 68

    const int qt  = (gridDim.x - 1) - blockIdx.x;  // heavy blocks first
    const int h   = blockIdx.y;
    const int b   = blockIdx.z;
    const int tid = threadIdx.x;
    const size_t hbase = ((size_t)b * SS) * DD + h * HDIM;

    {
        const int lr = tid >> 1;
        const int lc = (tid & 1) * 32;
        const float* qp = Qg + hbase + (size_t)(qt * 128 + lr) * DD + lc;
        #pragma unroll
        for (int v = 0; v < 8; v++) {
            float4 x = *(const float4*)(qp + v * 4);
            const int k = lc + v * 4;
            Qs[(k + 0) * FSTRIDE + lr] = x.x * 0.125f;
            Qs[(k + 1) * FSTRIDE + lr] = x.y * 0.125f;
            Qs[(k + 2) * FSTRIDE + lr] = x.z * 0.125f;
            Qs[(k + 3) * FSTRIDE + lr] = x.w * 0.125f;
        }
    }

    const int tr = (tid >> 4) << 3;
    const int tc = (tid & 15) << 2;

    float m[8], l[8], o[8][4];
    #pragma unroll
    for (int i = 0; i < 8; i++) {
        m[i] = -1e30f; l[i] = 0.f;
        #pragma unroll
        for (int j = 0; j < 4; j++) o[i][j] = 0.f;
    }

    const int nkt = 2 * qt + 2;
    const int lr = tid >> 2;
    const int lc = (tid & 3) * 16;

    for (int kt = 0; kt < nkt; kt++) {
        __syncthreads();
        {
            const float* kp = Kg + hbase + (size_t)(kt * 64 + lr) * DD + lc;
            #pragma unroll
            for (int v = 0; v < 4; v++) {
                float4 x = *(const float4*)(kp + v * 4);
                const int k = lc + v * 4;
                KPs[(k + 0) * FSTRIDE + lr] = x.x;
                KPs[(k + 1) * FSTRIDE + lr] = x.y;
                KPs[(k + 2) * FSTRIDE + lr] = x.z;
                KPs[(k + 3) * FSTRIDE + lr] = x.w;
            }
            const float* vp = Vg + hbase + (size_t)(kt * 64 + lr) * DD + lc;
            #pragma unroll
            for (int v = 0; v < 4; v++)
                *(float4*)&Vs[lr * VSTRIDE + lc + v * 4] = *(const float4*)(vp + v * 4);
        }
        __syncthreads();

        float s[8][4];
        #pragma unroll
        for (int i = 0; i < 8; i++)
            #pragma unroll
            for (int j = 0; j < 4; j++) s[i][j] = 0.f;

        #pragma unroll 4
        for (int k = 0; k < 64; k++) {
            float a[8], bb[4];
            *(float4*)&a[0] = *(const float4*)&Qs[k * FSTRIDE + tr];
            *(float4*)&a[4] = *(const float4*)&Qs[k * FSTRIDE + tr + 4];
            *(float4*)&bb[0] = *(const float4*)&KPs[k * FSTRIDE + tc];
            #pragma unroll
            for (int i = 0; i < 8; i++)
                #pragma unroll
                for (int j = 0; j < 4; j++)
                    s[i][j] = fmaf(a[i], bb[j], s[i][j]);
        }

        if (kt >= 2 * qt) {
            const int off = (kt - 2 * qt) * 64;
            #pragma unroll
            for (int i = 0; i < 8; i++)
                #pragma unroll
                for (int j = 0; j < 4; j++)
                    if (off + tc + j > tr + i) s[i][j] = -1e30f;
        }

        #pragma unroll
        for (int i = 0; i < 8; i++) {
            float mt = fmaxf(fmaxf(s[i][0], s[i][1]), fmaxf(s[i][2], s[i][3]));
            mt = fmaxf(mt, __shfl_xor_sync(0xffffffffu, mt, 1));
            mt = fmaxf(mt, __shfl_xor_sync(0xffffffffu, mt, 2));
            mt = fmaxf(mt, __shfl_xor_sync(0xffffffffu, mt, 4));
            mt = fmaxf(mt, __shfl_xor_sync(0xffffffffu, mt, 8));
            const float mn = fmaxf(m[i], mt);
            const float alpha = __expf(m[i] - mn);
            m[i] = mn;
            float ls = 0.f;
            #pragma unroll
            for (int j = 0; j < 4; j++) {
                const float p = __expf(s[i][j] - mn);
                s[i][j] = p;
                ls += p;
            }
            ls += __shfl_xor_sync(0xffffffffu, ls, 1);
            ls += __shfl_xor_sync(0xffffffffu, ls, 2);
            ls += __shfl_xor_sync(0xffffffffu, ls, 4);
            ls += __shfl_xor_sync(0xffffffffu, ls, 8);
            l[i] = l[i] * alpha + ls;
            #pragma unroll
            for (int j = 0; j < 4; j++) o[i][j] *= alpha;
        }

        __syncthreads();
        #pragma unroll
        for (int j = 0; j < 4; j++) {
            *(float4*)&KPs[(tc + j) * FSTRIDE + tr] =
                make_float4(s[0][j], s[1][j], s[2][j], s[3][j]);
            *(float4*)&KPs[(tc + j) * FSTRIDE + tr + 4] =
                make_float4(s[4][j], s[5][j], s[6][j], s[7][j]);
        }
        __syncthreads();

        #pragma unroll 4
        for (int c = 0; c < 64; c++) {
            float a[8], vv[4];
            *(float4*)&a[0] = *(const float4*)&KPs[c * FSTRIDE + tr];
            *(float4*)&a[4] = *(const float4*)&KPs[c * FSTRIDE + tr + 4];
            *(float4*)&vv[0] = *(const float4*)&Vs[c * VSTRIDE + tc];
            #pragma unroll
            for (int i = 0; i < 8; i++)
                #pragma unroll
                for (int j = 0; j < 4; j++)
                    o[i][j] = fmaf(a[i], vv[j], o[i][j]);
        }
    }

    #pragma unroll
    for (int i = 0; i < 8; i++) {
        const float inv = 1.0f / l[i];
        float4 r = make_float4(o[i][0] * inv, o[i][1] * inv, o[i][2] * inv, o[i][3] * inv);
        *(float4*)(Og + hbase + (size_t)(qt * 128 + tr + i) * DD + tc) = r;
    }
}

// ---------------- launch ----------------
extern "C" void kernel_launch(void* const* d_in, const int* in_sizes, int n_in,
                              void* d_out, int out_size)
{
    const float* queries = (const float*)d_in[0];
    const float* keys    = (const float*)d_in[1];
    // d_in[2] values: dead (reference projects V from projected K)
    // d_in[3] mask: causal tril, implemented analytically
    const float* Wq = (const float*)d_in[4];
    const float* bq = (const float*)d_in[5];
    const float* Wk = (const float*)d_in[6];
    const float* bk = (const float*)d_in[7];
    const float* Wv = (const float*)d_in[8];
    const float* bv = (const float*)d_in[9];
    const float* Wo = (const float*)d_in[10];
    const float* bo = (const float*)d_in[11];
    float* out = (float*)d_out;

    float *q, *k, *v, *a;
    cudaGetSymbolAddress((void**)&q, g_q);
    cudaGetSymbolAddress((void**)&k, g_k);
    cudaGetSymbolAddress((void**)&v, g_v);
    cudaGetSymbolAddress((void**)&a, g_a);

    cudaFuncSetAttribute(tc_gemm_kernel, cudaFuncAttributeMaxDynamicSharedMemorySize,
                         TC_SMEM);
    cudaFuncSetAttribute(flash_kernel, cudaFuncAttributeMaxDynamicSharedMemorySize,
                         FSMEM_BYTES);

    dim3 gblk(256);
    dim3 ggrid(DD / 128, MROWS / 128);   // (8, 32)

    tc_gemm_kernel<<<ggrid, gblk, TC_SMEM>>>(queries, Wq, bq, q);
    tc_gemm_kernel<<<ggrid, gblk, TC_SMEM>>>(keys,    Wk, bk, k);
    tc_gemm_kernel<<<ggrid, gblk, TC_SMEM>>>(k,       Wv, bv, v);

    dim3 fgrid(SS / 128, HH, BB);        // (16, 16, 2)
    flash_kernel<<<fgrid, dim3(256), FSMEM_BYTES>>>(q, k, v, a);

    tc_gemm_kernel<<<ggrid, gblk, TC_SMEM>>>(a, Wo, bo, out);
}

// round 4
// speedup vs baseline: 2.1874x; 1.5776x over previous
#include <cuda_runtime.h>
#include <cuda_bf16.h>
#include <cstdint>

// Problem constants
#define BB   2
#define SS   2048
#define DD   1024
#define HH   16
#define HDIM 64
#define MROWS (BB*SS)      // 4096

// ---------------- scratch (no allocations allowed) ----------------
__device__ float g_q[MROWS * DD];
__device__ float g_k[MROWS * DD];
__device__ float g_v[MROWS * DD];
__device__ float g_a[MROWS * DD];

// ============================================================================
// mma.sync helpers (baseline PTX — plain sm_103 target)
// ============================================================================
__device__ __forceinline__ uint32_t smem_u32(const void* p) {
    uint32_t a;
    asm("{ .reg .u64 t; cvta.to.shared.u64 t, %1; cvt.u32.u64 %0, t; }"
        : "=r"(a) : "l"(p));
    return a;
}

__device__ __forceinline__ void ldsm4(uint32_t* r, uint32_t addr) {
    asm volatile("ldmatrix.sync.aligned.m8n8.x4.shared.b16 {%0,%1,%2,%3}, [%4];"
                 : "=r"(r[0]), "=r"(r[1]), "=r"(r[2]), "=r"(r[3]) : "r"(addr));
}

__device__ __forceinline__ void ldsm4t(uint32_t* r, uint32_t addr) {
    asm volatile("ldmatrix.sync.aligned.m8n8.x4.trans.shared.b16 {%0,%1,%2,%3}, [%4];"
                 : "=r"(r[0]), "=r"(r[1]), "=r"(r[2]), "=r"(r[3]) : "r"(addr));
}

__device__ __forceinline__ void mma16816(float* c, const uint32_t* a,
                                         uint32_t b0, uint32_t b1) {
    asm volatile(
        "mma.sync.aligned.m16n8k16.row.col.f32.bf16.bf16.f32 "
        "{%0,%1,%2,%3}, {%4,%5,%6,%7}, {%8,%9}, {%0,%1,%2,%3};"
        : "+f"(c[0]), "+f"(c[1]), "+f"(c[2]), "+f"(c[3])
        : "r"(a[0]), "r"(a[1]), "r"(a[2]), "r"(a[3]), "r"(b0), "r"(b1));
}

__device__ __forceinline__ void split8(const float* v, uint4& hi, uint4& lo) {
    uint32_t h[8], l[8];
    #pragma unroll
    for (int i = 0; i < 8; i++) {
        __nv_bfloat16 bh = __float2bfloat16(v[i]);
        float r = v[i] - __bfloat162float(bh);
        __nv_bfloat16 bl = __float2bfloat16(r);
        h[i] = (uint32_t)__bfloat16_as_ushort(bh);
        l[i] = (uint32_t)__bfloat16_as_ushort(bl);
    }
    hi = make_uint4(h[0] | (h[1] << 16), h[2] | (h[3] << 16),
                    h[4] | (h[5] << 16), h[6] | (h[7] << 16));
    lo = make_uint4(l[0] | (l[1] << 16), l[2] | (l[3] << 16),
                    l[4] | (l[5] << 16), l[6] | (l[7] << 16));
}

__device__ __forceinline__ void splitpack(float x, float y, uint32_t& hi, uint32_t& lo) {
    __nv_bfloat16 hx = __float2bfloat16(x), hy = __float2bfloat16(y);
    float rx = x - __bfloat162float(hx);
    float ry = y - __bfloat162float(hy);
    __nv_bfloat16 lx = __float2bfloat16(rx), ly = __float2bfloat16(ry);
    hi = (uint32_t)__bfloat16_as_ushort(hx) | ((uint32_t)__bfloat16_as_ushort(hy) << 16);
    lo = (uint32_t)__bfloat16_as_ushort(lx) | ((uint32_t)__bfloat16_as_ushort(ly) << 16);
}

// ============================================================================
// bf16-split tensor-core GEMM (unchanged from R3): C[4096,1024] = A @ W + bias
// ============================================================================
#define TCH   64
#define TSTR  72
#define TILE_BYTES (128 * TSTR * 2)
#define SM_AHI 0
#define SM_ALO (SM_AHI + TILE_BYTES)
#define SM_BHI (SM_ALO + TILE_BYTES)
#define SM_BLO (SM_BHI + TILE_BYTES)
#define TC_SMEM (SM_BLO + TILE_BYTES)  // 73728

__global__ __launch_bounds__(256, 2)
void tc_gemm_kernel(const float* __restrict__ A, const float* __restrict__ W,
                    const float* __restrict__ bias, float* __restrict__ C)
{
    extern __shared__ char smem[];
    const uint32_t sb = smem_u32(smem);
    const int tid  = threadIdx.x;
    const int wid  = tid >> 5;
    const int lane = tid & 31;
    const int bn = blockIdx.x;
    const int bm = blockIdx.y;

    const int mw = wid >> 1;
    const int nw = wid & 1;

    const int ar  = tid >> 1;
    const int akh = (tid & 1) * 32;
    const int bnl = tid & 127;
    const int bkh = (tid >> 7) * 32;

    const float* Ap = A + (size_t)(bm * 128 + ar) * DD + akh;
    const float* Wp = W + (size_t)bkh * DD + bn * 128 + bnl;

    const int lrow = lane & 15;
    const int lkof = (lane >> 4) << 3;

    const uint32_t aAddr0 = sb + (uint32_t)(((mw * 32 + lrow) * TSTR + lkof) * 2);
    const uint32_t aAddr1 = aAddr0 + 16 * TSTR * 2;
    const uint32_t bAddr  = sb + (uint32_t)(((nw * 64 + lrow) * TSTR + lkof) * 2);

    float acc[2][8][4];
    #pragma unroll
    for (int i = 0; i < 2; i++)
        #pragma unroll
        for (int j = 0; j < 8; j++)
            #pragma unroll
            for (int q = 0; q < 4; q++) acc[i][j][q] = 0.f;

    for (int c = 0; c < DD / TCH; c++) {
        if (c) __syncthreads();
        #pragma unroll
        for (int g = 0; g < 4; g++) {
            float v[8];
            *(float4*)&v[0] = *(const float4*)(Ap + c * TCH + g * 8);
            *(float4*)&v[4] = *(const float4*)(Ap + c * TCH + g * 8 + 4);
            uint4 hi, lo;
            split8(v, hi, lo);
            const uint32_t off = (uint32_t)((ar * TSTR + akh + g * 8) * 2);
            *(uint4*)(smem + SM_AHI + off) = hi;
            *(uint4*)(smem + SM_ALO + off) = lo;
        }
        #pragma unroll
        for (int g = 0; g < 4; g++) {
            float v[8];
            #pragma unroll
            for (int i = 0; i < 8; i++)
                v[i] = Wp[(size_t)(c * TCH + g * 8 + i) * DD];
            uint4 hi, lo;
            split8(v, hi, lo);
            const uint32_t off = (uint32_t)((bnl * TSTR + bkh + g * 8) * 2);
            *(uint4*)(smem + SM_BHI + off) = hi;
            *(uint4*)(smem + SM_BLO + off) = lo;
        }
        __syncthreads();

        #pragma unroll
        for (int ks = 0; ks < TCH / 16; ks++) {
            const uint32_t kb = ks * 32;
            uint32_t ahi[2][4], alo[2][4];
            ldsm4(ahi[0], aAddr0 + SM_AHI + kb);
            ldsm4(ahi[1], aAddr1 + SM_AHI + kb);
            ldsm4(alo[0], aAddr0 + SM_ALO + kb);
            ldsm4(alo[1], aAddr1 + SM_ALO + kb);
            #pragma unroll
            for (int np = 0; np < 4; np++) {
                uint32_t bhi[4], blo[4];
                const uint32_t bofs = (uint32_t)(np * 16 * TSTR * 2) + kb;
                ldsm4(bhi, bAddr + SM_BHI + bofs);
                ldsm4(blo, bAddr + SM_BLO + bofs);
                #pragma unroll
                for (int half = 0; half < 2; half++) {
                    const uint32_t bh0 = bhi[half], bh1 = bhi[half + 2];
                    const uint32_t bl0 = blo[half], bl1 = blo[half + 2];
                    #pragma unroll
                    for (int mi = 0; mi < 2; mi++) {
                        float* cc = acc[mi][np * 2 + half];
                        mma16816(cc, ahi[mi], bh0, bh1);
                        mma16816(cc, ahi[mi], bl0, bl1);
                        mma16816(cc, alo[mi], bh0, bh1);
                    }
                }
            }
        }
    }

    const int tg = lane >> 2;
    const int tq = lane & 3;
    #pragma unroll
    for (int mi = 0; mi < 2; mi++) {
        const int gr0 = bm * 128 + mw * 32 + mi * 16 + tg;
        #pragma unroll
        for (int nj = 0; nj < 8; nj++) {
            const int gc = bn * 128 + nw * 64 + nj * 8 + tq * 2;
            const float b0 = bias[gc], b1 = bias[gc + 1];
            float* c0 = &acc[mi][nj][0];
            *(float2*)(C + (size_t)gr0 * DD + gc) =
                make_float2(c0[0] + b0, c0[1] + b1);
            *(float2*)(C + (size_t)(gr0 + 8) * DD + gc) =
                make_float2(c0[2] + b0, c0[3] + b1);
        }
    }
}

// ============================================================================
// flash attention: mma.sync bf16-split, causal
// BR=128 q rows x BC=64 keys per tile; 8 warps, each warp = 16 q rows.
// smem (bf16, stride 72): Qhi/Qlo [128x64], Khi/Klo [64x64], Vhi/Vlo [64x64].
// ============================================================================
#define FQHI 0
#define FQLO 18432
#define FKHI 36864
#define FKLO 46080
#define FVHI 55296
#define FVLO 64512
#define FLASH_SMEM 73728

__global__ __launch_bounds__(256, 2)
void flash_kernel(const float* __restrict__ Qg, const float* __restrict__ Kg,
                  const float* __restrict__ Vg, float* __restrict__ Og)
{
    extern __shared__ char smem[];
    const uint32_t sb = smem_u32(smem);
    const int tid  = threadIdx.x;
    const int wid  = tid >> 5;
    const int lane = tid & 31;
    const int qt = (gridDim.x - 1) - blockIdx.x;   // heavy blocks first
    const int h  = blockIdx.y;
    const int b  = blockIdx.z;
    const size_t hbase = ((size_t)b * SS) * DD + h * HDIM;

    // ---- Q tile load: 128 x 64, pre-scaled by 1/sqrt(64)=0.125, split hi/lo ----
    {
        const int lr = tid >> 1;
        const int lc = (tid & 1) * 32;
        const float* qp = Qg + hbase + (size_t)(qt * 128 + lr) * DD + lc;
        #pragma unroll
        for (int g = 0; g < 4; g++) {
            float v[8];
            *(float4*)&v[0] = *(const float4*)(qp + g * 8);
            *(float4*)&v[4] = *(const float4*)(qp + g * 8 + 4);
            #pragma unroll
            for (int i = 0; i < 8; i++) v[i] *= 0.125f;
            uint4 hi, lo;
            split8(v, hi, lo);
            const uint32_t off = (uint32_t)((lr * 72 + lc + g * 8) * 2);
            *(uint4*)(smem + FQHI + off) = hi;
            *(uint4*)(smem + FQLO + off) = lo;
        }
    }

    const int lrow = lane & 15;
    const int lkof = (lane >> 4) << 3;
    const uint32_t qA = sb + FQHI + (uint32_t)(((wid * 16 + lrow) * 72 + lkof) * 2);
    const uint32_t kA = sb + FKHI + (uint32_t)((lrow * 72 + lkof) * 2);
    const uint32_t vA = sb + FVHI + (uint32_t)((lrow * 72 + lkof) * 2);

    float oacc[8][4];
    #pragma unroll
    for (int t = 0; t < 8; t++)
        #pragma unroll
        for (int j = 0; j < 4; j++) oacc[t][j] = 0.f;
    float m0 = -1e30f, m1 = -1e30f, l0 = 0.f, l1 = 0.f;

    const int nkt = 2 * qt + 2;
    const int klr = tid >> 2;          // key row 0..63
    const int klc = (tid & 3) * 16;    // d chunk

    for (int kt = 0; kt < nkt; kt++) {
        __syncthreads();   // prev-iter smem reads done (covers Q store on kt=0)
        {
            const float* kp = Kg + hbase + (size_t)(kt * 64 + klr) * DD + klc;
            const float* vp = Vg + hbase + (size_t)(kt * 64 + klr) * DD + klc;
            #pragma unroll
            for (int g = 0; g < 2; g++) {
                const uint32_t off = (uint32_t)((klr * 72 + klc + g * 8) * 2);
                float v[8];
                *(float4*)&v[0] = *(const float4*)(kp + g * 8);
                *(float4*)&v[4] = *(const float4*)(kp + g * 8 + 4);
                uint4 hi, lo;
                split8(v, hi, lo);
                *(uint4*)(smem + FKHI + off) = hi;
                *(uint4*)(smem + FKLO + off) = lo;
                *(float4*)&v[0] = *(const float4*)(vp + g * 8);
                *(float4*)&v[4] = *(const float4*)(vp + g * 8 + 4);
                split8(v, hi, lo);
                *(uint4*)(smem + FVHI + off) = hi;
                *(uint4*)(smem + FVLO + off) = lo;
            }
        }
        __syncthreads();

        // ---- S = Q K^T (3-pass bf16 split), warp computes 16 rows x 64 keys ----
        float s[8][4];
        #pragma unroll
        for (int t = 0; t < 8; t++)
            #pragma unroll
            for (int j = 0; j < 4; j++) s[t][j] = 0.f;

        #pragma unroll
        for (int ks = 0; ks < 4; ks++) {
            uint32_t qhi[4], qlo[4];
            ldsm4(qhi, qA + ks * 32);
            ldsm4(qlo, qA + (FQLO - FQHI) + ks * 32);
            #pragma unroll
            for (int np = 0; np < 4; np++) {
                uint32_t khi[4], klo[4];
                const uint32_t ko = (uint32_t)(np * 2304 + ks * 32);
                ldsm4(khi, kA + ko);
                ldsm4(klo, kA + (FKLO - FKHI) + ko);
                #pragma unroll
                for (int hf = 0; hf < 2; hf++) {
                    float* cc = s[np * 2 + hf];
                    mma16816(cc, qhi, khi[hf], khi[hf + 2]);
                    mma16816(cc, qhi, klo[hf], klo[hf + 2]);
                    mma16816(cc, qlo, khi[hf], khi[hf + 2]);
                }
            }
        }

        // ---- causal mask (only the two diagonal-adjacent tiles) ----
        if (kt >= 2 * qt) {
            const int off = (kt - 2 * qt) * 64;
            const int r0 = wid * 16 + (lane >> 2);
            const int cb = (lane & 3) * 2;
            #pragma unroll
            for (int t = 0; t < 8; t++)
                #pragma unroll
                for (int j = 0; j < 2; j++) {
                    const int cg = off + t * 8 + cb + j;
                    if (cg > r0)     s[t][j]     = -1e30f;
                    if (cg > r0 + 8) s[t][2 + j] = -1e30f;
                }
        }

        // ---- online softmax on fragments (quad shuffles) ----
        float mx0 = -1e30f, mx1 = -1e30f;
        #pragma unroll
        for (int t = 0; t < 8; t++) {
            mx0 = fmaxf(mx0, fmaxf(s[t][0], s[t][1]));
            mx1 = fmaxf(mx1, fmaxf(s[t][2], s[t][3]));
        }
        mx0 = fmaxf(mx0, __shfl_xor_sync(0xffffffffu, mx0, 1));
        mx0 = fmaxf(mx0, __shfl_xor_sync(0xffffffffu, mx0, 2));
        mx1 = fmaxf(mx1, __shfl_xor_sync(0xffffffffu, mx1, 1));
        mx1 = fmaxf(mx1, __shfl_xor_sync(0xffffffffu, mx1, 2));

        const float mn0 = fmaxf(m0, mx0);
        const float mn1 = fmaxf(m1, mx1);
        const float al0 = __expf(m0 - mn0);
        const float al1 = __expf(m1 - mn1);
        m0 = mn0; m1 = mn1;

        float ls0 = 0.f, ls1 = 0.f;
        #pragma unroll
        for (int t = 0; t < 8; t++) {
            s[t][0] = __expf(s[t][0] - mn0); ls0 += s[t][0];
            s[t][1] = __expf(s[t][1] - mn0); ls0 += s[t][1];
            s[t][2] = __expf(s[t][2] - mn1); ls1 += s[t][2];
            s[t][3] = __expf(s[t][3] - mn1); ls1 += s[t][3];
        }
        ls0 += __shfl_xor_sync(0xffffffffu, ls0, 1);
        ls0 += __shfl_xor_sync(0xffffffffu, ls0, 2);
        ls1 += __shfl_xor_sync(0xffffffffu, ls1, 1);
        ls1 += __shfl_xor_sync(0xffffffffu, ls1, 2);
        l0 = l0 * al0 + ls0;
        l1 = l1 * al1 + ls1;
        #pragma unroll
        for (int t = 0; t < 8; t++) {
            oacc[t][0] *= al0; oacc[t][1] *= al0;
            oacc[t][2] *= al1; oacc[t][3] *= al1;
        }

        // ---- O += P V (3-pass bf16 split), P frags built in-register ----
        #pragma unroll
        for (int t = 0; t < 4; t++) {
            uint32_t aPhi[4], aPlo[4];
            splitpack(s[2 * t][0],     s[2 * t][1],     aPhi[0], aPlo[0]);
            splitpack(s[2 * t][2],     s[2 * t][3],     aPhi[1], aPlo[1]);
            splitpack(s[2 * t + 1][0], s[2 * t + 1][1], aPhi[2], aPlo[2]);
            splitpack(s[2 * t + 1][2], s[2 * t + 1][3], aPhi[3], aPlo[3]);
            #pragma unroll
            for (int np = 0; np < 4; np++) {
                uint32_t vhi[4], vlo[4];
                const uint32_t vo = (uint32_t)(t * 2304 + np * 32);
                ldsm4t(vhi, vA + vo);
                ldsm4t(vlo, vA + (FVLO - FVHI) + vo);
                #pragma unroll
                for (int hf = 0; hf < 2; hf++) {
                    float* cc = oacc[np * 2 + hf];
                    mma16816(cc, aPhi, vhi[2 * hf], vhi[2 * hf + 1]);
                    mma16816(cc, aPhi, vlo[2 * hf], vlo[2 * hf + 1]);
                    mma16816(cc, aPlo, vhi[2 * hf], vhi[2 * hf + 1]);
                }
            }
        }
    }

    // ---- epilogue: normalize, store to (b, s, h*64 + d) ----
    const float inv0 = 1.0f / l0;
    const float inv1 = 1.0f / l1;
    const int r0 = qt * 128 + wid * 16 + (lane >> 2);
    const int cb = (lane & 3) * 2;
    #pragma unroll
    for (int t = 0; t < 8; t++) {
        *(float2*)(Og + hbase + (size_t)r0 * DD + t * 8 + cb) =
            make_float2(oacc[t][0] * inv0, oacc[t][1] * inv0);
        *(float2*)(Og + hbase + (size_t)(r0 + 8) * DD + t * 8 + cb) =
            make_float2(oacc[t][2] * inv1, oacc[t][3] * inv1);
    }
}

// ---------------- launch ----------------
extern "C" void kernel_launch(void* const* d_in, const int* in_sizes, int n_in,
                              void* d_out, int out_size)
{
    const float* queries = (const float*)d_in[0];
    const float* keys    = (const float*)d_in[1];
    // d_in[2] values: dead (reference projects V from projected K)
    // d_in[3] mask: causal tril, implemented analytically
    const float* Wq = (const float*)d_in[4];
    const float* bq = (const float*)d_in[5];
    const float* Wk = (const float*)d_in[6];
    const float* bk = (const float*)d_in[7];
    const float* Wv = (const float*)d_in[8];
    const float* bv = (const float*)d_in[9];
    const float* Wo = (const float*)d_in[10];
    const float* bo = (const float*)d_in[11];
    float* out = (float*)d_out;

    float *q, *k, *v, *a;
    cudaGetSymbolAddress((void**)&q, g_q);
    cudaGetSymbolAddress((void**)&k, g_k);
    cudaGetSymbolAddress((void**)&v, g_v);
    cudaGetSymbolAddress((void**)&a, g_a);

    cudaFuncSetAttribute(tc_gemm_kernel, cudaFuncAttributeMaxDynamicSharedMemorySize,
                         TC_SMEM);
    cudaFuncSetAttribute(flash_kernel, cudaFuncAttributeMaxDynamicSharedMemorySize,
                         FLASH_SMEM);

    dim3 gblk(256);
    dim3 ggrid(DD / 128, MROWS / 128);   // (8, 32)

    tc_gemm_kernel<<<ggrid, gblk, TC_SMEM>>>(queries, Wq, bq, q);
    tc_gemm_kernel<<<ggrid, gblk, TC_SMEM>>>(keys,    Wk, bk, k);
    tc_gemm_kernel<<<ggrid, gblk, TC_SMEM>>>(k,       Wv, bv, v);

    dim3 fgrid(SS / 128, HH, BB);        // (16, 16, 2)
    flash_kernel<<<fgrid, dim3(256), FLASH_SMEM>>>(q, k, v, a);

    tc_gemm_kernel<<<ggrid, gblk, TC_SMEM>>>(a, Wo, bo, out);
}

// round 5
// speedup vs baseline: 2.3927x; 1.0938x over previous
#include <cuda_runtime.h>
#include <cuda_bf16.h>
#include <cstdint>

// Problem constants
#define BB   2
#define SS   2048
#define DD   1024
#define HH   16
#define HDIM 64
#define MROWS (BB*SS)      // 4096
typedef __nv_bfloat16 bf16;

// ---------------- scratch (no allocations allowed) ----------------
// split inputs (GEMM A operands)
__device__ bf16 g_inqh[MROWS * DD], g_inql[MROWS * DD];
__device__ bf16 g_inkh[MROWS * DD], g_inkl[MROWS * DD];
// split+transposed weights [n][k]
__device__ bf16 g_wqh[DD * DD], g_wql[DD * DD];
__device__ bf16 g_wkh[DD * DD], g_wkl[DD * DD];
__device__ bf16 g_wvh[DD * DD], g_wvl[DD * DD];
__device__ bf16 g_woh[DD * DD], g_wol[DD * DD];
// projected activations (hi/lo)
__device__ bf16 g_qh[MROWS * DD], g_ql[MROWS * DD];
__device__ bf16 g_kh[MROWS * DD], g_kl[MROWS * DD];
__device__ bf16 g_vh[MROWS * DD], g_vl[MROWS * DD];
__device__ bf16 g_ah[MROWS * DD], g_al[MROWS * DD];

// ============================================================================
// helpers
// ============================================================================
__device__ __forceinline__ uint32_t smem_u32(const void* p) {
    uint32_t a;
    asm("{ .reg .u64 t; cvta.to.shared.u64 t, %1; cvt.u32.u64 %0, t; }"
        : "=r"(a) : "l"(p));
    return a;
}
__device__ __forceinline__ void ldsm4(uint32_t* r, uint32_t addr) {
    asm volatile("ldmatrix.sync.aligned.m8n8.x4.shared.b16 {%0,%1,%2,%3}, [%4];"
                 : "=r"(r[0]), "=r"(r[1]), "=r"(r[2]), "=r"(r[3]) : "r"(addr));
}
__device__ __forceinline__ void ldsm4t(uint32_t* r, uint32_t addr) {
    asm volatile("ldmatrix.sync.aligned.m8n8.x4.trans.shared.b16 {%0,%1,%2,%3}, [%4];"
                 : "=r"(r[0]), "=r"(r[1]), "=r"(r[2]), "=r"(r[3]) : "r"(addr));
}
__device__ __forceinline__ void mma16816(float* c, const uint32_t* a,
                                         uint32_t b0, uint32_t b1) {
    asm volatile(
        "mma.sync.aligned.m16n8k16.row.col.f32.bf16.bf16.f32 "
        "{%0,%1,%2,%3}, {%4,%5,%6,%7}, {%8,%9}, {%0,%1,%2,%3};"
        : "+f"(c[0]), "+f"(c[1]), "+f"(c[2]), "+f"(c[3])
        : "r"(a[0]), "r"(a[1]), "r"(a[2]), "r"(a[3]), "r"(b0), "r"(b1));
}
__device__ __forceinline__ void splitpack(float x, float y, uint32_t& hi, uint32_t& lo) {
    bf16 hx = __float2bfloat16(x), hy = __float2bfloat16(y);
    float rx = x - __bfloat162float(hx);
    float ry = y - __bfloat162float(hy);
    bf16 lx = __float2bfloat16(rx), ly = __float2bfloat16(ry);
    hi = (uint32_t)__bfloat16_as_ushort(hx) | ((uint32_t)__bfloat16_as_ushort(hy) << 16);
    lo = (uint32_t)__bfloat16_as_ushort(lx) | ((uint32_t)__bfloat16_as_ushort(ly) << 16);
}

#define CP_ASYNC16(dst, src) \
    asm volatile("cp.async.cg.shared.global [%0], [%1], 16;" \
                 :: "r"(dst), "l"(src) : "memory")
#define CP_COMMIT() asm volatile("cp.async.commit_group;" ::: "memory")
#define CP_WAIT0()  asm volatile("cp.async.wait_group 0;" ::: "memory")
#define CP_WAIT1()  asm volatile("cp.async.wait_group 1;" ::: "memory")

// ============================================================================
// split kernels (run once per launch; memory-bound)
// ============================================================================
__global__ void split_kernel(const float* __restrict__ src,
                             bf16* __restrict__ hi, bf16* __restrict__ lo)
{
    const int i = (blockIdx.x * 256 + threadIdx.x) * 4;
    float4 v = *(const float4*)(src + i);
    uint32_t h0, l0, h1, l1;
    splitpack(v.x, v.y, h0, l0);
    splitpack(v.z, v.w, h1, l1);
    *(uint2*)(hi + i) = make_uint2(h0, h1);
    *(uint2*)(lo + i) = make_uint2(l0, l1);
}

// W [k][n] fp32 -> Wt [n][k] bf16 hi/lo, via smem tile transpose
__global__ void splitw_kernel(const float* __restrict__ W,
                              bf16* __restrict__ th, bf16* __restrict__ tl)
{
    __shared__ float t[32][33];
    const int tx = threadIdx.x, ty = threadIdx.y;
    const int k0 = blockIdx.y * 32, n0 = blockIdx.x * 32;
    #pragma unroll
    for (int i = 0; i < 4; i++)
        t[ty + i * 8][tx] = W[(size_t)(k0 + ty + i * 8) * DD + n0 + tx];
    __syncthreads();
    #pragma unroll
    for (int i = 0; i < 4; i++) {
        const float v = t[tx][ty + i * 8];
        bf16 h = __float2bfloat16(v);
        bf16 l = __float2bfloat16(v - __bfloat162float(h));
        const size_t o = (size_t)(n0 + ty + i * 8) * DD + k0 + tx;
        th[o] = h; tl[o] = l;
    }
}

// ============================================================================
// GEMM: C[4096,1024] = (Ahi+Alo) @ (Bhi+Blo)^T_layout + bias, 3-pass bf16.
// A [m][k] bf16 pairs, B pre-transposed [n][k] bf16 pairs.
// CTA 128x128, K-chunk 32, 2-stage cp.async, SW64-swizzled smem.
// Output: bf16 hi/lo pairs (F32OUT=false) or fp32 (F32OUT=true).
// ============================================================================
#define GSTG 32768   // stage: AHI 8K | ALO 8K | BHI 8K | BLO 8K
#define GEMM_SMEM (2 * GSTG)

template<bool F32OUT>
__global__ __launch_bounds__(256, 2)
void gemm_bf16_kernel(const bf16* __restrict__ Ah, const bf16* __restrict__ Al,
                      const bf16* __restrict__ Bh, const bf16* __restrict__ Bl,
                      const float* __restrict__ bias, float scale,
                      bf16* __restrict__ Ch, bf16* __restrict__ Cl,
                      float* __restrict__ Cf)
{
    extern __shared__ char smem[];
    const uint32_t sb = smem_u32(smem);
    const int tid = threadIdx.x, wid = tid >> 5, lane = tid & 31;
    const int bn = blockIdx.x, bm = blockIdx.y;
    const int mw = wid >> 1, nw = wid & 1;

    // loader: thread -> row lr (0..127), chunk cols lc0, lc0+1 (16B units)
    const int lr = tid >> 1, lc0 = (tid & 1) * 2;
    const bf16* rAh = Ah + (size_t)(bm * 128 + lr) * DD;
    const bf16* rAl = Al + (size_t)(bm * 128 + lr) * DD;
    const bf16* rBh = Bh + (size_t)(bn * 128 + lr) * DD;
    const bf16* rBl = Bl + (size_t)(bn * 128 + lr) * DD;
    // SW64 swizzle for 64B rows: chunk' = c16 ^ ((r>>1)&3)
    const uint32_t xl = (lr >> 1) & 3;
    uint32_t ldst[2];
    #pragma unroll
    for (int j = 0; j < 2; j++)
        ldst[j] = (uint32_t)(lr * 64 + ((lc0 + j) ^ xl) * 16);

    // ldsm addressing
    const int lrow = lane & 15, cl = lane >> 4;
    const uint32_t xg = (lrow >> 1) & 3;
    uint32_t offA[2][2], offB[4][2];
    #pragma unroll
    for (int ks = 0; ks < 2; ks++) {
        const uint32_t cc = (uint32_t)(((ks * 2 + cl) ^ xg) * 16);
        #pragma unroll
        for (int mi = 0; mi < 2; mi++)
            offA[mi][ks] = (uint32_t)((mw * 32 + mi * 16 + lrow) * 64) + cc;
        #pragma unroll
        for (int np = 0; np < 4; np++)
            offB[np][ks] = (uint32_t)((nw * 64 + np * 16 + lrow) * 64) + cc;
    }

    float acc[2][8][4];
    #pragma unroll
    for (int i = 0; i < 2; i++)
        #pragma unroll
        for (int j = 0; j < 8; j++)
            #pragma unroll
            for (int q = 0; q < 4; q++) acc[i][j][q] = 0.f;

    // prologue: stage 0
    {
        const uint32_t base = sb;
        #pragma unroll
        for (int j = 0; j < 2; j++) {
            const int eo = (lc0 + j) * 8;
            CP_ASYNC16(base + ldst[j],         rAh + eo);
            CP_ASYNC16(base + 8192 + ldst[j],  rAl + eo);
            CP_ASYNC16(base + 16384 + ldst[j], rBh + eo);
            CP_ASYNC16(base + 24576 + ldst[j], rBl + eo);
        }
        CP_COMMIT();
    }

    for (int kc = 0; kc < 32; kc++) {
        if (kc + 1 < 32) {
            const uint32_t base = sb + ((kc + 1) & 1) * GSTG;
            const int ke = (kc + 1) * 32;
            #pragma unroll
            for (int j = 0; j < 2; j++) {
                const int eo = ke + (lc0 + j) * 8;
                CP_ASYNC16(base + ldst[j],         rAh + eo);
                CP_ASYNC16(base + 8192 + ldst[j],  rAl + eo);
                CP_ASYNC16(base + 16384 + ldst[j], rBh + eo);
                CP_ASYNC16(base + 24576 + ldst[j], rBl + eo);
            }
            CP_COMMIT();
            CP_WAIT1();
        } else {
            CP_WAIT0();
        }
        __syncthreads();

        const uint32_t B0 = sb + (kc & 1) * GSTG;
        #pragma unroll
        for (int ks = 0; ks < 2; ks++) {
            uint32_t ah[2][4], al[2][4];
            ldsm4(ah[0], B0 + offA[0][ks]);
            ldsm4(ah[1], B0 + offA[1][ks]);
            ldsm4(al[0], B0 + 8192 + offA[0][ks]);
            ldsm4(al[1], B0 + 8192 + offA[1][ks]);
            #pragma unroll
            for (int np = 0; np < 4; np++) {
                uint32_t bh[4], bl[4];
                ldsm4(bh, B0 + 16384 + offB[np][ks]);
                ldsm4(bl, B0 + 24576 + offB[np][ks]);
                #pragma unroll
                for (int hf = 0; hf < 2; hf++) {
                    #pragma unroll
                    for (int mi = 0; mi < 2; mi++) {
                        float* cc = acc[mi][np * 2 + hf];
                        mma16816(cc, ah[mi], bh[hf], bh[hf + 2]);
                        mma16816(cc, ah[mi], bl[hf], bl[hf + 2]);
                        mma16816(cc, al[mi], bh[hf], bh[hf + 2]);
                    }
                }
            }
        }
        __syncthreads();
    }

    // epilogue
    const int tg = lane >> 2, tq = lane & 3;
    #pragma unroll
    for (int mi = 0; mi < 2; mi++) {
        const int gr = bm * 128 + mw * 32 + mi * 16 + tg;
        #pragma unroll
        for (int nj = 0; nj < 8; nj++) {
            const int gc = bn * 128 + nw * 64 + nj * 8 + tq * 2;
            const float b0 = bias[gc], b1 = bias[gc + 1];
            float* c = acc[mi][nj];
            const float v0 = (c[0] + b0) * scale, v1 = (c[1] + b1) * scale;
            const float v2 = (c[2] + b0) * scale, v3 = (c[3] + b1) * scale;
            if (F32OUT) {
                *(float2*)(Cf + (size_t)gr * DD + gc)       = make_float2(v0, v1);
                *(float2*)(Cf + (size_t)(gr + 8) * DD + gc) = make_float2(v2, v3);
            } else {
                uint32_t h, l;
                splitpack(v0, v1, h, l);
                *(uint32_t*)(Ch + (size_t)gr * DD + gc) = h;
                *(uint32_t*)(Cl + (size_t)gr * DD + gc) = l;
                splitpack(v2, v3, h, l);
                *(uint32_t*)(Ch + (size_t)(gr + 8) * DD + gc) = h;
                *(uint32_t*)(Cl + (size_t)(gr + 8) * DD + gc) = l;
            }
        }
    }
}

// ============================================================================
// flash attention v2: pre-split bf16 Q/K/V, SW128 smem, 2-stage cp.async K/V.
// BR=128 q rows x BC=64 keys; 8 warps x 16 q rows.
// smem: QHI 16K | QLO 16K | stage{KHI 8K|KLO 8K|VHI 8K|VLO 8K} x2 = 96K.
// ============================================================================
#define FKV0 32768
#define FKVSTG 32768
#define FLASH_SMEM 98304

__global__ __launch_bounds__(256, 2)
void flash_kernel(const bf16* __restrict__ Qh, const bf16* __restrict__ Ql,
                  const bf16* __restrict__ Kh, const bf16* __restrict__ Kl,
                  const bf16* __restrict__ Vh, const bf16* __restrict__ Vl,
                  bf16* __restrict__ Oh, bf16* __restrict__ Ol)
{
    extern __shared__ char smem[];
    const uint32_t sb = smem_u32(smem);
    const int tid = threadIdx.x, wid = tid >> 5, lane = tid & 31;
    const int qt = (gridDim.x - 1) - blockIdx.x;   // heavy blocks first
    const int h = blockIdx.y, b = blockIdx.z;
    const size_t hbase = ((size_t)b * SS) * DD + h * HDIM;
    const int nkt = 2 * qt + 2;

    // ---- loaders ----
    // Q: thread -> row qlr (0..127), chunks qc0..qc0+3
    const int qlr = tid >> 1, qc0 = (tid & 1) * 4;
    // K/V: thread -> row klr (0..63), chunks kc0, kc0+1
    const int klr = tid >> 2, kc0 = (tid & 3) * 2;
    const bf16* rQh = Qh + hbase + (size_t)(qt * 128 + qlr) * DD;
    const bf16* rQl = Ql + hbase + (size_t)(qt * 128 + qlr) * DD;
    const bf16* rKh = Kh + hbase + (size_t)klr * DD;
    const bf16* rKl = Kl + hbase + (size_t)klr * DD;
    const bf16* rVh = Vh + hbase + (size_t)klr * DD;
    const bf16* rVl = Vl + hbase + (size_t)klr * DD;
    // SW128 for 128B rows: chunk' = c16 ^ (r&7)
    const uint32_t qx = qlr & 7, kx = klr & 7;

    // prologue: Q + KV stage 0 in group 0
    #pragma unroll
    for (int j = 0; j < 4; j++) {
        const uint32_t d = (uint32_t)(qlr * 128 + ((qc0 + j) ^ qx) * 16);
        const int eo = (qc0 + j) * 8;
        CP_ASYNC16(sb + d,         rQh + eo);
        CP_ASYNC16(sb + 16384 + d, rQl + eo);
    }
    #pragma unroll
    for (int j = 0; j < 2; j++) {
        const uint32_t d = (uint32_t)(klr * 128 + ((kc0 + j) ^ kx) * 16);
        const int eo = (kc0 + j) * 8;
        CP_ASYNC16(sb + FKV0 + d,         rKh + eo);
        CP_ASYNC16(sb + FKV0 + 8192 + d,  rKl + eo);
        CP_ASYNC16(sb + FKV0 + 16384 + d, rVh + eo);
        CP_ASYNC16(sb + FKV0 + 24576 + d, rVl + eo);
    }
    CP_COMMIT();

    // ldsm addressing
    const int lrow = lane & 15, cl = lane >> 4;
    const uint32_t x = lrow & 7;
    const uint32_t rb = (uint32_t)(lrow * 128);
    const uint32_t qwb = (uint32_t)(wid * 2048);

    float oacc[8][4];
    #pragma unroll
    for (int t = 0; t < 8; t++)
        #pragma unroll
        for (int j = 0; j < 4; j++) oacc[t][j] = 0.f;
    float m0 = -1e30f, m1 = -1e30f, l0 = 0.f, l1 = 0.f;

    for (int kt = 0; kt < nkt; kt++) {
        if (kt + 1 < nkt) {
            const uint32_t base = sb + FKV0 + ((kt + 1) & 1) * FKVSTG;
            const size_t ro = (size_t)(kt + 1) * 64 * DD;
            #pragma unroll
            for (int j = 0; j < 2; j++) {
                const uint32_t d = (uint32_t)(klr * 128 + ((kc0 + j) ^ kx) * 16);
                const int eo = (kc0 + j) * 8;
                CP_ASYNC16(base + d,         rKh + ro + eo);
                CP_ASYNC16(base + 8192 + d,  rKl + ro + eo);
                CP_ASYNC16(base + 16384 + d, rVh + ro + eo);
                CP_ASYNC16(base + 24576 + d, rVl + ro + eo);
            }
            CP_COMMIT();
            CP_WAIT1();
        } else {
            CP_WAIT0();
        }
        __syncthreads();

        const uint32_t kvb = sb + FKV0 + (kt & 1) * FKVSTG;

        // ---- S = Q K^T (3-pass) ----
        float s[8][4];
        #pragma unroll
        for (int t = 0; t < 8; t++)
            #pragma unroll
            for (int j = 0; j < 4; j++) s[t][j] = 0.f;

        #pragma unroll
        for (int ks = 0; ks < 4; ks++) {
            const uint32_t cc = ((uint32_t)(ks * 2 + cl) ^ x) * 16;
            uint32_t qhi[4], qlo[4];
            ldsm4(qhi, sb + qwb + rb + cc);
            ldsm4(qlo, sb + 16384 + qwb + rb + cc);
            #pragma unroll
            for (int np = 0; np < 4; np++) {
                uint32_t khi[4], klo[4];
                const uint32_t ko = kvb + (uint32_t)(np * 2048) + rb + cc;
                ldsm4(khi, ko);
                ldsm4(klo, ko + 8192);
                #pragma unroll
                for (int hf = 0; hf < 2; hf++) {
                    float* cs = s[np * 2 + hf];
                    mma16816(cs, qhi, khi[hf], khi[hf + 2]);
                    mma16816(cs, qhi, klo[hf], klo[hf + 2]);
                    mma16816(cs, qlo, khi[hf], khi[hf + 2]);
                }
            }
        }

        // ---- causal mask ----
        if (kt >= 2 * qt) {
            const int off = (kt - 2 * qt) * 64;
            const int r0 = wid * 16 + (lane >> 2);
            const int cb = (lane & 3) * 2;
            #pragma unroll
            for (int t = 0; t < 8; t++)
                #pragma unroll
                for (int j = 0; j < 2; j++) {
                    const int cg = off + t * 8 + cb + j;
                    if (cg > r0)     s[t][j]     = -1e30f;
                    if (cg > r0 + 8) s[t][2 + j] = -1e30f;
                }
        }

        // ---- online softmax ----
        float mx0 = -1e30f, mx1 = -1e30f;
        #pragma unroll
        for (int t = 0; t < 8; t++) {
            mx0 = fmaxf(mx0, fmaxf(s[t][0], s[t][1]));
            mx1 = fmaxf(mx1, fmaxf(s[t][2], s[t][3]));
        }
        mx0 = fmaxf(mx0, __shfl_xor_sync(0xffffffffu, mx0, 1));
        mx0 = fmaxf(mx0, __shfl_xor_sync(0xffffffffu, mx0, 2));
        mx1 = fmaxf(mx1, __shfl_xor_sync(0xffffffffu, mx1, 1));
        mx1 = fmaxf(mx1, __shfl_xor_sync(0xffffffffu, mx1, 2));

        const float mn0 = fmaxf(m0, mx0);
        const float mn1 = fmaxf(m1, mx1);
        const float al0 = __expf(m0 - mn0);
        const float al1 = __expf(m1 - mn1);
        m0 = mn0; m1 = mn1;

        float ls0 = 0.f, ls1 = 0.f;
        #pragma unroll
        for (int t = 0; t < 8; t++) {
            s[t][0] = __expf(s[t][0] - mn0); ls0 += s[t][0];
            s[t][1] = __expf(s[t][1] - mn0); ls0 += s[t][1];
            s[t][2] = __expf(s[t][2] - mn1); ls1 += s[t][2];
            s[t][3] = __expf(s[t][3] - mn1); ls1 += s[t][3];
        }
        ls0 += __shfl_xor_sync(0xffffffffu, ls0, 1);
        ls0 += __shfl_xor_sync(0xffffffffu, ls0, 2);
        ls1 += __shfl_xor_sync(0xffffffffu, ls1, 1);
        ls1 += __shfl_xor_sync(0xffffffffu, ls1, 2);
        l0 = l0 * al0 + ls0;
        l1 = l1 * al1 + ls1;
        #pragma unroll
        for (int t = 0; t < 8; t++) {
            oacc[t][0] *= al0; oacc[t][1] *= al0;
            oacc[t][2] *= al1; oacc[t][3] *= al1;
        }

        // ---- O += P V (3-pass) ----
        #pragma unroll
        for (int t = 0; t < 4; t++) {
            uint32_t aPhi[4], aPlo[4];
            splitpack(s[2 * t][0],     s[2 * t][1],     aPhi[0], aPlo[0]);
            splitpack(s[2 * t][2],     s[2 * t][3],     aPhi[1], aPlo[1]);
            splitpack(s[2 * t + 1][0], s[2 * t + 1][1], aPhi[2], aPlo[2]);
            splitpack(s[2 * t + 1][2], s[2 * t + 1][3], aPhi[3], aPlo[3]);
            #pragma unroll
            for (int np = 0; np < 4; np++) {
                const uint32_t cc = ((uint32_t)(np * 2 + cl) ^ x) * 16;
                const uint32_t vo = kvb + 16384 + (uint32_t)(t * 2048) + rb + cc;
                uint32_t vhi[4], vlo[4];
                ldsm4t(vhi, vo);
                ldsm4t(vlo, vo + 8192);
                #pragma unroll
                for (int hf = 0; hf < 2; hf++) {
                    float* cc2 = oacc[np * 2 + hf];
                    mma16816(cc2, aPhi, vhi[2 * hf], vhi[2 * hf + 1]);
                    mma16816(cc2, aPhi, vlo[2 * hf], vlo[2 * hf + 1]);
                    mma16816(cc2, aPlo, vhi[2 * hf], vhi[2 * hf + 1]);
                }
            }
        }
        __syncthreads();
    }

    // ---- epilogue: normalize, split, store hi/lo ----
    const float inv0 = 1.0f / l0;
    const float inv1 = 1.0f / l1;
    const int r0 = qt * 128 + wid * 16 + (lane >> 2);
    const int cb = (lane & 3) * 2;
    #pragma unroll
    for (int t = 0; t < 8; t++) {
        uint32_t h0, lo0, h1, lo1;
        splitpack(oacc[t][0] * inv0, oacc[t][1] * inv0, h0, lo0);
        splitpack(oacc[t][2] * inv1, oacc[t][3] * inv1, h1, lo1);
        const size_t o0 = hbase + (size_t)r0 * DD + t * 8 + cb;
        const size_t o1 = hbase + (size_t)(r0 + 8) * DD + t * 8 + cb;
        *(uint32_t*)(Oh + o0) = h0;
        *(uint32_t*)(Ol + o0) = lo0;
        *(uint32_t*)(Oh + o1) = h1;
        *(uint32_t*)(Ol + o1) = lo1;
    }
}

// ---------------- launch ----------------
extern "C" void kernel_launch(void* const* d_in, const int* in_sizes, int n_in,
                              void* d_out, int out_size)
{
    const float* queries = (const float*)d_in[0];
    const float* keys    = (const float*)d_in[1];
    // d_in[2] values: dead (reference projects V from projected K)
    // d_in[3] mask: causal tril, analytic
    const float* Wq = (const float*)d_in[4];
    const float* bq = (const float*)d_in[5];
    const float* Wk = (const float*)d_in[6];
    const float* bk = (const float*)d_in[7];
    const float* Wv = (const float*)d_in[8];
    const float* bv = (const float*)d_in[9];
    const float* Wo = (const float*)d_in[10];
    const float* bo = (const float*)d_in[11];
    float* out = (float*)d_out;

    bf16 *inqh, *inql, *inkh, *inkl;
    bf16 *wqh, *wql, *wkh, *wkl, *wvh, *wvl, *woh, *wol;
    bf16 *qh, *ql, *kh, *kl, *vh, *vl, *ah, *al;
    cudaGetSymbolAddress((void**)&inqh, g_inqh); cudaGetSymbolAddress((void**)&inql, g_inql);
    cudaGetSymbolAddress((void**)&inkh, g_inkh); cudaGetSymbolAddress((void**)&inkl, g_inkl);
    cudaGetSymbolAddress((void**)&wqh, g_wqh); cudaGetSymbolAddress((void**)&wql, g_wql);
    cudaGetSymbolAddress((void**)&wkh, g_wkh); cudaGetSymbolAddress((void**)&wkl, g_wkl);
    cudaGetSymbolAddress((void**)&wvh, g_wvh); cudaGetSymbolAddress((void**)&wvl, g_wvl);
    cudaGetSymbolAddress((void**)&woh, g_woh); cudaGetSymbolAddress((void**)&wol, g_wol);
    cudaGetSymbolAddress((void**)&qh, g_qh); cudaGetSymbolAddress((void**)&ql, g_ql);
    cudaGetSymbolAddress((void**)&kh, g_kh); cudaGetSymbolAddress((void**)&kl, g_kl);
    cudaGetSymbolAddress((void**)&vh, g_vh); cudaGetSymbolAddress((void**)&vl, g_vl);
    cudaGetSymbolAddress((void**)&ah, g_ah); cudaGetSymbolAddress((void**)&al, g_al);

    cudaFuncSetAttribute(gemm_bf16_kernel<false>,
                         cudaFuncAttributeMaxDynamicSharedMemorySize, GEMM_SMEM);
    cudaFuncSetAttribute(gemm_bf16_kernel<true>,
                         cudaFuncAttributeMaxDynamicSharedMemorySize, GEMM_SMEM);
    cudaFuncSetAttribute(flash_kernel,
                         cudaFuncAttributeMaxDynamicSharedMemorySize, FLASH_SMEM);

    // 1) splits
    const int selem = MROWS * DD;                   // 4M
    split_kernel<<<selem / 1024, 256>>>(queries, inqh, inql);
    split_kernel<<<selem / 1024, 256>>>(keys,    inkh, inkl);
    dim3 wtb(32, 8), wtg(32, 32);
    splitw_kernel<<<wtg, wtb>>>(Wq, wqh, wql);
    splitw_kernel<<<wtg, wtb>>>(Wk, wkh, wkl);
    splitw_kernel<<<wtg, wtb>>>(Wv, wvh, wvl);
    splitw_kernel<<<wtg, wtb>>>(Wo, woh, wol);

    // 2) projections (q scaled by 1/sqrt(HD)=0.125 in epilogue)
    dim3 gblk(256), ggrid(DD / 128, MROWS / 128);   // (8, 32)
    gemm_bf16_kernel<false><<<ggrid, gblk, GEMM_SMEM>>>(
        inqh, inql, wqh, wql, bq, 0.125f, qh, ql, nullptr);
    gemm_bf16_kernel<false><<<ggrid, gblk, GEMM_SMEM>>>(
        inkh, inkl, wkh, wkl, bk, 1.0f, kh, kl, nullptr);
    gemm_bf16_kernel<false><<<ggrid, gblk, GEMM_SMEM>>>(
        kh, kl, wvh, wvl, bv, 1.0f, vh, vl, nullptr);

    // 3) attention
    dim3 fgrid(SS / 128, HH, BB);                   // (16, 16, 2)
    flash_kernel<<<fgrid, dim3(256), FLASH_SMEM>>>(qh, ql, kh, kl, vh, vl, ah, al);

    // 4) output projection -> fp32 out
    gemm_bf16_kernel<true><<<ggrid, gblk, GEMM_SMEM>>>(
        ah, al, woh, wol, bo, 1.0f, nullptr, nullptr, out);
}

// round 7
// speedup vs baseline: 2.4248x; 1.0134x over previous
#include <cuda_runtime.h>
#include <cuda_bf16.h>
#include <cstdint>

// Problem constants
#define BB   2
#define SS   2048
#define DD   1024
#define HH   16
#define HDIM 64
#define MROWS (BB*SS)      // 4096
typedef __nv_bfloat16 bf16;

// ---------------- scratch (no allocations allowed) ----------------
__device__ bf16 g_inqh[MROWS * DD], g_inql[MROWS * DD];
__device__ bf16 g_inkh[MROWS * DD], g_inkl[MROWS * DD];
__device__ bf16 g_wqh[DD * DD], g_wql[DD * DD];
__device__ bf16 g_wkh[DD * DD], g_wkl[DD * DD];
__device__ bf16 g_wvh[DD * DD], g_wvl[DD * DD];
__device__ bf16 g_woh[DD * DD], g_wol[DD * DD];
__device__ bf16 g_qh[MROWS * DD], g_ql[MROWS * DD];
__device__ bf16 g_kh[MROWS * DD], g_kl[MROWS * DD];
__device__ bf16 g_vh[MROWS * DD], g_vl[MROWS * DD];
__device__ bf16 g_ah[MROWS * DD], g_al[MROWS * DD];

// ============================================================================
// helpers
// ============================================================================
__device__ __forceinline__ uint32_t smem_u32(const void* p) {
    uint32_t a;
    asm("{ .reg .u64 t; cvta.to.shared.u64 t, %1; cvt.u32.u64 %0, t; }"
        : "=r"(a) : "l"(p));
    return a;
}
__device__ __forceinline__ void ldsm4(uint32_t* r, uint32_t addr) {
    asm volatile("ldmatrix.sync.aligned.m8n8.x4.shared.b16 {%0,%1,%2,%3}, [%4];"
                 : "=r"(r[0]), "=r"(r[1]), "=r"(r[2]), "=r"(r[3]) : "r"(addr));
}
__device__ __forceinline__ void ldsm4t(uint32_t* r, uint32_t addr) {
    asm volatile("ldmatrix.sync.aligned.m8n8.x4.trans.shared.b16 {%0,%1,%2,%3}, [%4];"
                 : "=r"(r[0]), "=r"(r[1]), "=r"(r[2]), "=r"(r[3]) : "r"(addr));
}
__device__ __forceinline__ void mma16816(float* c, const uint32_t* a,
                                         uint32_t b0, uint32_t b1) {
    asm volatile(
        "mma.sync.aligned.m16n8k16.row.col.f32.bf16.bf16.f32 "
        "{%0,%1,%2,%3}, {%4,%5,%6,%7}, {%8,%9}, {%0,%1,%2,%3};"
        : "+f"(c[0]), "+f"(c[1]), "+f"(c[2]), "+f"(c[3])
        : "r"(a[0]), "r"(a[1]), "r"(a[2]), "r"(a[3]), "r"(b0), "r"(b1));
}
__device__ __forceinline__ void splitpack(float x, float y, uint32_t& hi, uint32_t& lo) {
    bf16 hx = __float2bfloat16(x), hy = __float2bfloat16(y);
    float rx = x - __bfloat162float(hx);
    float ry = y - __bfloat162float(hy);
    bf16 lx = __float2bfloat16(rx), ly = __float2bfloat16(ry);
    hi = (uint32_t)__bfloat16_as_ushort(hx) | ((uint32_t)__bfloat16_as_ushort(hy) << 16);
    lo = (uint32_t)__bfloat16_as_ushort(lx) | ((uint32_t)__bfloat16_as_ushort(ly) << 16);
}

#define CP_ASYNC16(dst, src) \
    asm volatile("cp.async.cg.shared.global [%0], [%1], 16;" \
                 :: "r"(dst), "l"(src) : "memory")
#define CP_COMMIT() asm volatile("cp.async.commit_group;" ::: "memory")
#define CP_WAIT0()  asm volatile("cp.async.wait_group 0;" ::: "memory")
#define CP_WAIT1()  asm volatile("cp.async.wait_group 1;" ::: "memory")
#define CP_WAIT2()  asm volatile("cp.async.wait_group 2;" ::: "memory")

// ============================================================================
// fused split kernels
// ============================================================================
__global__ void split_fused_kernel(const float* __restrict__ s0, bf16* h0, bf16* l0,
                                   const float* __restrict__ s1, bf16* h1, bf16* l1)
{
    const float* src = blockIdx.z ? s1 : s0;
    bf16* hi = blockIdx.z ? h1 : h0;
    bf16* lo = blockIdx.z ? l1 : l0;
    const int i = (blockIdx.x * 256 + threadIdx.x) * 4;
    float4 v = *(const float4*)(src + i);
    uint32_t a0, b0, a1, b1;
    splitpack(v.x, v.y, a0, b0);
    splitpack(v.z, v.w, a1, b1);
    *(uint2*)(hi + i) = make_uint2(a0, a1);
    *(uint2*)(lo + i) = make_uint2(b0, b1);
}

__global__ void splitw_fused_kernel(
    const float* __restrict__ W0, bf16* th0, bf16* tl0,
    const float* __restrict__ W1, bf16* th1, bf16* tl1,
    const float* __restrict__ W2, bf16* th2, bf16* tl2,
    const float* __restrict__ W3, bf16* th3, bf16* tl3)
{
    const float* W; bf16* th; bf16* tl;
    switch (blockIdx.z) {
        case 0: W = W0; th = th0; tl = tl0; break;
        case 1: W = W1; th = th1; tl = tl1; break;
        case 2: W = W2; th = th2; tl = tl2; break;
        default: W = W3; th = th3; tl = tl3; break;
    }
    __shared__ float t[32][33];
    const int tx = threadIdx.x, ty = threadIdx.y;
    const int k0 = blockIdx.y * 32, n0 = blockIdx.x * 32;
    #pragma unroll
    for (int i = 0; i < 4; i++)
        t[ty + i * 8][tx] = W[(size_t)(k0 + ty + i * 8) * DD + n0 + tx];
    __syncthreads();
    #pragma unroll
    for (int i = 0; i < 4; i++) {
        const float v = t[tx][ty + i * 8];
        bf16 h = __float2bfloat16(v);
        bf16 l = __float2bfloat16(v - __bfloat162float(h));
        const size_t o = (size_t)(n0 + ty + i * 8) * DD + k0 + tx;
        th[o] = h; tl[o] = l;
    }
}

// ============================================================================
// GEMM: C = (Ahi+Alo) @ (Bhi+Blo)^T + bias; 3-pass bf16; 3-stage cp.async.
// RACE FIX vs R6: prefetch issued AFTER __syncthreads — the barrier guarantees
// all warps finished reading the stage being overwritten (stage (kc-1)%3).
// ============================================================================
#define GSTG 32768   // stage: AHI 8K | ALO 8K | BHI 8K | BLO 8K
#define GEMM_SMEM (3 * GSTG)   // 98304

template<bool F32OUT>
__global__ __launch_bounds__(256, 2)
void gemm_bf16_kernel(const bf16* __restrict__ Ah, const bf16* __restrict__ Al,
                      const bf16* __restrict__ Bh, const bf16* __restrict__ Bl,
                      const float* __restrict__ bias, float scale,
                      bf16* __restrict__ Ch, bf16* __restrict__ Cl,
                      float* __restrict__ Cf)
{
    extern __shared__ char smem[];
    const uint32_t sb = smem_u32(smem);
    const int tid = threadIdx.x, wid = tid >> 5, lane = tid & 31;
    const int bn = blockIdx.x, bm = blockIdx.y;
    const int mw = wid >> 1, nw = wid & 1;

    const int lr = tid >> 1, lc0 = (tid & 1) * 2;
    const bf16* rAh = Ah + (size_t)(bm * 128 + lr) * DD;
    const bf16* rAl = Al + (size_t)(bm * 128 + lr) * DD;
    const bf16* rBh = Bh + (size_t)(bn * 128 + lr) * DD;
    const bf16* rBl = Bl + (size_t)(bn * 128 + lr) * DD;
    const uint32_t xl = (lr >> 1) & 3;
    uint32_t ldst[2];
    #pragma unroll
    for (int j = 0; j < 2; j++)
        ldst[j] = (uint32_t)(lr * 64 + ((lc0 + j) ^ xl) * 16);

    const int lrow = lane & 15, cl = lane >> 4;
    const uint32_t xg = (lrow >> 1) & 3;
    uint32_t offA[2][2], offB[4][2];
    #pragma unroll
    for (int ks = 0; ks < 2; ks++) {
        const uint32_t cc = (uint32_t)(((ks * 2 + cl) ^ xg) * 16);
        #pragma unroll
        for (int mi = 0; mi < 2; mi++)
            offA[mi][ks] = (uint32_t)((mw * 32 + mi * 16 + lrow) * 64) + cc;
        #pragma unroll
        for (int np = 0; np < 4; np++)
            offB[np][ks] = (uint32_t)((nw * 64 + np * 16 + lrow) * 64) + cc;
    }

    float acc[2][8][4];
    #pragma unroll
    for (int i = 0; i < 2; i++)
        #pragma unroll
        for (int j = 0; j < 8; j++)
            #pragma unroll
            for (int q = 0; q < 4; q++) acc[i][j][q] = 0.f;

    // prologue: stages 0, 1 (chunks 0, 1)
    #pragma unroll
    for (int st = 0; st < 2; st++) {
        const uint32_t base = sb + st * GSTG;
        const int ke = st * 32;
        #pragma unroll
        for (int j = 0; j < 2; j++) {
            const int eo = ke + (lc0 + j) * 8;
            CP_ASYNC16(base + ldst[j],         rAh + eo);
            CP_ASYNC16(base + 8192 + ldst[j],  rAl + eo);
            CP_ASYNC16(base + 16384 + ldst[j], rBh + eo);
            CP_ASYNC16(base + 24576 + ldst[j], rBl + eo);
        }
        CP_COMMIT();
    }

    int stage = 0;
    for (int kc = 0; kc < 32; kc++) {
        // barrier FIRST: all warps done reading stage (kc-1)%3 == prefetch target
        __syncthreads();

        if (kc + 2 < 32) {
            const uint32_t base = sb + ((stage + 2) % 3) * GSTG;
            const int ke = (kc + 2) * 32;
            #pragma unroll
            for (int j = 0; j < 2; j++) {
                const int eo = ke + (lc0 + j) * 8;
                CP_ASYNC16(base + ldst[j],         rAh + eo);
                CP_ASYNC16(base + 8192 + ldst[j],  rAl + eo);
                CP_ASYNC16(base + 16384 + ldst[j], rBh + eo);
                CP_ASYNC16(base + 24576 + ldst[j], rBl + eo);
            }
            CP_COMMIT();
            CP_WAIT2();   // retire group for chunk kc
        } else if (kc + 1 < 32) {
            CP_WAIT1();
        } else {
            CP_WAIT0();
        }

        const uint32_t B0 = sb + stage * GSTG;
        #pragma unroll
        for (int ks = 0; ks < 2; ks++) {
            uint32_t ah[2][4], al[2][4];
            ldsm4(ah[0], B0 + offA[0][ks]);
            ldsm4(ah[1], B0 + offA[1][ks]);
            ldsm4(al[0], B0 + 8192 + offA[0][ks]);
            ldsm4(al[1], B0 + 8192 + offA[1][ks]);
            #pragma unroll
            for (int np = 0; np < 4; np++) {
                uint32_t bh[4], bl[4];
                ldsm4(bh, B0 + 16384 + offB[np][ks]);
                ldsm4(bl, B0 + 24576 + offB[np][ks]);
                #pragma unroll
                for (int hf = 0; hf < 2; hf++) {
                    #pragma unroll
                    for (int mi = 0; mi < 2; mi++) {
                        float* cc = acc[mi][np * 2 + hf];
                        mma16816(cc, ah[mi], bh[hf], bh[hf + 2]);
                        mma16816(cc, ah[mi], bl[hf], bl[hf + 2]);
                        mma16816(cc, al[mi], bh[hf], bh[hf + 2]);
                    }
                }
            }
        }
        stage = (stage + 1) % 3;
    }

    // epilogue
    const int tg = lane >> 2, tq = lane & 3;
    #pragma unroll
    for (int mi = 0; mi < 2; mi++) {
        const int gr = bm * 128 + mw * 32 + mi * 16 + tg;
        #pragma unroll
        for (int nj = 0; nj < 8; nj++) {
            const int gc = bn * 128 + nw * 64 + nj * 8 + tq * 2;
            const float b0 = bias[gc], b1 = bias[gc + 1];
            float* c = acc[mi][nj];
            const float v0 = (c[0] + b0) * scale, v1 = (c[1] + b1) * scale;
            const float v2 = (c[2] + b0) * scale, v3 = (c[3] + b1) * scale;
            if (F32OUT) {
                *(float2*)(Cf + (size_t)gr * DD + gc)       = make_float2(v0, v1);
                *(float2*)(Cf + (size_t)(gr + 8) * DD + gc) = make_float2(v2, v3);
            } else {
                uint32_t h, l;
                splitpack(v0, v1, h, l);
                *(uint32_t*)(Ch + (size_t)gr * DD + gc) = h;
                *(uint32_t*)(Cl + (size_t)gr * DD + gc) = l;
                splitpack(v2, v3, h, l);
                *(uint32_t*)(Ch + (size_t)(gr + 8) * DD + gc) = h;
                *(uint32_t*)(Cl + (size_t)(gr + 8) * DD + gc) = l;
            }
        }
    }
}

// ============================================================================
// flash attention (unchanged from passing R5): pre-split bf16, SW128, 2-stage KV.
// ============================================================================
#define FKV0 32768
#define FKVSTG 32768
#define FLASH_SMEM 98304

__global__ __launch_bounds__(256, 2)
void flash_kernel(const bf16* __restrict__ Qh, const bf16* __restrict__ Ql,
                  const bf16* __restrict__ Kh, const bf16* __restrict__ Kl,
                  const bf16* __restrict__ Vh, const bf16* __restrict__ Vl,
                  bf16* __restrict__ Oh, bf16* __restrict__ Ol)
{
    extern __shared__ char smem[];
    const uint32_t sb = smem_u32(smem);
    const int tid = threadIdx.x, wid = tid >> 5, lane = tid & 31;
    const int qt = (gridDim.x - 1) - blockIdx.x;
    const int h = blockIdx.y, b = blockIdx.z;
    const size_t hbase = ((size_t)b * SS) * DD + h * HDIM;
    const int nkt = 2 * qt + 2;

    const int qlr = tid >> 1, qc0 = (tid & 1) * 4;
    const int klr = tid >> 2, kc0 = (tid & 3) * 2;
    const bf16* rQh = Qh + hbase + (size_t)(qt * 128 + qlr) * DD;
    const bf16* rQl = Ql + hbase + (size_t)(qt * 128 + qlr) * DD;
    const bf16* rKh = Kh + hbase + (size_t)klr * DD;
    const bf16* rKl = Kl + hbase + (size_t)klr * DD;
    const bf16* rVh = Vh + hbase + (size_t)klr * DD;
    const bf16* rVl = Vl + hbase + (size_t)klr * DD;
    const uint32_t qx = qlr & 7, kx = klr & 7;

    #pragma unroll
    for (int j = 0; j < 4; j++) {
        const uint32_t d = (uint32_t)(qlr * 128 + ((qc0 + j) ^ qx) * 16);
        const int eo = (qc0 + j) * 8;
        CP_ASYNC16(sb + d,         rQh + eo);
        CP_ASYNC16(sb + 16384 + d, rQl + eo);
    }
    #pragma unroll
    for (int j = 0; j < 2; j++) {
        const uint32_t d = (uint32_t)(klr * 128 + ((kc0 + j) ^ kx) * 16);
        const int eo = (kc0 + j) * 8;
        CP_ASYNC16(sb + FKV0 + d,         rKh + eo);
        CP_ASYNC16(sb + FKV0 + 8192 + d,  rKl + eo);
        CP_ASYNC16(sb + FKV0 + 16384 + d, rVh + eo);
        CP_ASYNC16(sb + FKV0 + 24576 + d, rVl + eo);
    }
    CP_COMMIT();

    const int lrow = lane & 15, cl = lane >> 4;
    const uint32_t x = lrow & 7;
    const uint32_t rb = (uint32_t)(lrow * 128);
    const uint32_t qwb = (uint32_t)(wid * 2048);

    float oacc[8][4];
    #pragma unroll
    for (int t = 0; t < 8; t++)
        #pragma unroll
        for (int j = 0; j < 4; j++) oacc[t][j] = 0.f;
    float m0 = -1e30f, m1 = -1e30f, l0 = 0.f, l1 = 0.f;

    for (int kt = 0; kt < nkt; kt++) {
        if (kt + 1 < nkt) {
            const uint32_t base = sb + FKV0 + ((kt + 1) & 1) * FKVSTG;
            const size_t ro = (size_t)(kt + 1) * 64 * DD;
            #pragma unroll
            for (int j = 0; j < 2; j++) {
                const uint32_t d = (uint32_t)(klr * 128 + ((kc0 + j) ^ kx) * 16);
                const int eo = (kc0 + j) * 8;
                CP_ASYNC16(base + d,         rKh + ro + eo);
                CP_ASYNC16(base + 8192 + d,  rKl + ro + eo);
                CP_ASYNC16(base + 16384 + d, rVh + ro + eo);
                CP_ASYNC16(base + 24576 + d, rVl + ro + eo);
            }
            CP_COMMIT();
            CP_WAIT1();
        } else {
            CP_WAIT0();
        }
        __syncthreads();

        const uint32_t kvb = sb + FKV0 + (kt & 1) * FKVSTG;

        float s[8][4];
        #pragma unroll
        for (int t = 0; t < 8; t++)
            #pragma unroll
            for (int j = 0; j < 4; j++) s[t][j] = 0.f;

        #pragma unroll
        for (int ks = 0; ks < 4; ks++) {
            const uint32_t cc = ((uint32_t)(ks * 2 + cl) ^ x) * 16;
            uint32_t qhi[4], qlo[4];
            ldsm4(qhi, sb + qwb + rb + cc);
            ldsm4(qlo, sb + 16384 + qwb + rb + cc);
            #pragma unroll
            for (int np = 0; np < 4; np++) {
                uint32_t khi[4], klo[4];
                const uint32_t ko = kvb + (uint32_t)(np * 2048) + rb + cc;
                ldsm4(khi, ko);
                ldsm4(klo, ko + 8192);
                #pragma unroll
                for (int hf = 0; hf < 2; hf++) {
                    float* cs = s[np * 2 + hf];
                    mma16816(cs, qhi, khi[hf], khi[hf + 2]);
                    mma16816(cs, qhi, klo[hf], klo[hf + 2]);
                    mma16816(cs, qlo, khi[hf], khi[hf + 2]);
                }
            }
        }

        if (kt >= 2 * qt) {
            const int off = (kt - 2 * qt) * 64;
            const int r0 = wid * 16 + (lane >> 2);
            const int cb = (lane & 3) * 2;
            #pragma unroll
            for (int t = 0; t < 8; t++)
                #pragma unroll
                for (int j = 0; j < 2; j++) {
                    const int cg = off + t * 8 + cb + j;
                    if (cg > r0)     s[t][j]     = -1e30f;
                    if (cg > r0 + 8) s[t][2 + j] = -1e30f;
                }
        }

        float mx0 = -1e30f, mx1 = -1e30f;
        #pragma unroll
        for (int t = 0; t < 8; t++) {
            mx0 = fmaxf(mx0, fmaxf(s[t][0], s[t][1]));
            mx1 = fmaxf(mx1, fmaxf(s[t][2], s[t][3]));
        }
        mx0 = fmaxf(mx0, __shfl_xor_sync(0xffffffffu, mx0, 1));
        mx0 = fmaxf(mx0, __shfl_xor_sync(0xffffffffu, mx0, 2));
        mx1 = fmaxf(mx1, __shfl_xor_sync(0xffffffffu, mx1, 1));
        mx1 = fmaxf(mx1, __shfl_xor_sync(0xffffffffu, mx1, 2));

        const float mn0 = fmaxf(m0, mx0);
        const float mn1 = fmaxf(m1, mx1);
        const float al0 = __expf(m0 - mn0);
        const float al1 = __expf(m1 - mn1);
        m0 = mn0; m1 = mn1;

        float ls0 = 0.f, ls1 = 0.f;
        #pragma unroll
        for (int t = 0; t < 8; t++) {
            s[t][0] = __expf(s[t][0] - mn0); ls0 += s[t][0];
            s[t][1] = __expf(s[t][1] - mn0); ls0 += s[t][1];
            s[t][2] = __expf(s[t][2] - mn1); ls1 += s[t][2];
            s[t][3] = __expf(s[t][3] - mn1); ls1 += s[t][3];
        }
        ls0 += __shfl_xor_sync(0xffffffffu, ls0, 1);
        ls0 += __shfl_xor_sync(0xffffffffu, ls0, 2);
        ls1 += __shfl_xor_sync(0xffffffffu, ls1, 1);
        ls1 += __shfl_xor_sync(0xffffffffu, ls1, 2);
        l0 = l0 * al0 + ls0;
        l1 = l1 * al1 + ls1;
        #pragma unroll
        for (int t = 0; t < 8; t++) {
            oacc[t][0] *= al0; oacc[t][1] *= al0;
            oacc[t][2] *= al1; oacc[t][3] *= al1;
        }

        #pragma unroll
        for (int t = 0; t < 4; t++) {
            uint32_t aPhi[4], aPlo[4];
            splitpack(s[2 * t][0],     s[2 * t][1],     aPhi[0], aPlo[0]);
            splitpack(s[2 * t][2],     s[2 * t][3],     aPhi[1], aPlo[1]);
            splitpack(s[2 * t + 1][0], s[2 * t + 1][1], aPhi[2], aPlo[2]);
            splitpack(s[2 * t + 1][2], s[2 * t + 1][3], aPhi[3], aPlo[3]);
            #pragma unroll
            for (int np = 0; np < 4; np++) {
                const uint32_t cc = ((uint32_t)(np * 2 + cl) ^ x) * 16;
                const uint32_t vo = kvb + 16384 + (uint32_t)(t * 2048) + rb + cc;
                uint32_t vhi[4], vlo[4];
                ldsm4t(vhi, vo);
                ldsm4t(vlo, vo + 8192);
                #pragma unroll
                for (int hf = 0; hf < 2; hf++) {
                    float* cc2 = oacc[np * 2 + hf];
                    mma16816(cc2, aPhi, vhi[2 * hf], vhi[2 * hf + 1]);
                    mma16816(cc2, aPhi, vlo[2 * hf], vlo[2 * hf + 1]);
                    mma16816(cc2, aPlo, vhi[2 * hf], vhi[2 * hf + 1]);
                }
            }
        }
        __syncthreads();
    }

    const float inv0 = 1.0f / l0;
    const float inv1 = 1.0f / l1;
    const int r0 = qt * 128 + wid * 16 + (lane >> 2);
    const int cb = (lane & 3) * 2;
    #pragma unroll
    for (int t = 0; t < 8; t++) {
        uint32_t h0, lo0, h1, lo1;
        splitpack(oacc[t][0] * inv0, oacc[t][1] * inv0, h0, lo0);
        splitpack(oacc[t][2] * inv1, oacc[t][3] * inv1, h1, lo1);
        const size_t o0 = hbase + (size_t)r0 * DD + t * 8 + cb;
        const size_t o1 = hbase + (size_t)(r0 + 8) * DD + t * 8 + cb;
        *(uint32_t*)(Oh + o0) = h0;
        *(uint32_t*)(Ol + o0) = lo0;
        *(uint32_t*)(Oh + o1) = h1;
        *(uint32_t*)(Ol + o1) = lo1;
    }
}

// ---------------- launch ----------------
extern "C" void kernel_launch(void* const* d_in, const int* in_sizes, int n_in,
                              void* d_out, int out_size)
{
    const float* queries = (const float*)d_in[0];
    const float* keys    = (const float*)d_in[1];
    const float* Wq = (const float*)d_in[4];
    const float* bq = (const float*)d_in[5];
    const float* Wk = (const float*)d_in[6];
    const float* bk = (const float*)d_in[7];
    const float* Wv = (const float*)d_in[8];
    const float* bv = (const float*)d_in[9];
    const float* Wo = (const float*)d_in[10];
    const float* bo = (const float*)d_in[11];
    float* out = (float*)d_out;

    bf16 *inqh, *inql, *inkh, *inkl;
    bf16 *wqh, *wql, *wkh, *wkl, *wvh, *wvl, *woh, *wol;
    bf16 *qh, *ql, *kh, *kl, *vh, *vl, *ah, *al;
    cudaGetSymbolAddress((void**)&inqh, g_inqh); cudaGetSymbolAddress((void**)&inql, g_inql);
    cudaGetSymbolAddress((void**)&inkh, g_inkh); cudaGetSymbolAddress((void**)&inkl, g_inkl);
    cudaGetSymbolAddress((void**)&wqh, g_wqh); cudaGetSymbolAddress((void**)&wql, g_wql);
    cudaGetSymbolAddress((void**)&wkh, g_wkh); cudaGetSymbolAddress((void**)&wkl, g_wkl);
    cudaGetSymbolAddress((void**)&wvh, g_wvh); cudaGetSymbolAddress((void**)&wvl, g_wvl);
    cudaGetSymbolAddress((void**)&woh, g_woh); cudaGetSymbolAddress((void**)&wol, g_wol);
    cudaGetSymbolAddress((void**)&qh, g_qh); cudaGetSymbolAddress((void**)&ql, g_ql);
    cudaGetSymbolAddress((void**)&kh, g_kh); cudaGetSymbolAddress((void**)&kl, g_kl);
    cudaGetSymbolAddress((void**)&vh, g_vh); cudaGetSymbolAddress((void**)&vl, g_vl);
    cudaGetSymbolAddress((void**)&ah, g_ah); cudaGetSymbolAddress((void**)&al, g_al);

    cudaFuncSetAttribute(gemm_bf16_kernel<false>,
                         cudaFuncAttributeMaxDynamicSharedMemorySize, GEMM_SMEM);
    cudaFuncSetAttribute(gemm_bf16_kernel<true>,
                         cudaFuncAttributeMaxDynamicSharedMemorySize, GEMM_SMEM);
    cudaFuncSetAttribute(flash_kernel,
                         cudaFuncAttributeMaxDynamicSharedMemorySize, FLASH_SMEM);

    // 1) fused splits (launches 1-2)
    const int selem = MROWS * DD;
    dim3 sgrid(selem / 1024, 1, 2);
    split_fused_kernel<<<sgrid, 256>>>(queries, inqh, inql, keys, inkh, inkl);
    dim3 wtb(32, 8), wtg(32, 32, 4);
    splitw_fused_kernel<<<wtg, wtb>>>(Wq, wqh, wql, Wk, wkh, wkl,
                                      Wv, wvh, wvl, Wo, woh, wol);

    // 2) projections (launches 3-5)
    dim3 gblk(256), ggrid(DD / 128, MROWS / 128);
    gemm_bf16_kernel<false><<<ggrid, gblk, GEMM_SMEM>>>(
        inqh, inql, wqh, wql, bq, 0.125f, qh, ql, nullptr);
    gemm_bf16_kernel<false><<<ggrid, gblk, GEMM_SMEM>>>(
        inkh, inkl, wkh, wkl, bk, 1.0f, kh, kl, nullptr);
    gemm_bf16_kernel<false><<<ggrid, gblk, GEMM_SMEM>>>(
        kh, kl, wvh, wvl, bv, 1.0f, vh, vl, nullptr);

    // 3) attention (launch 6 -> ncu -s 5 -c 1 captures THIS)
    dim3 fgrid(SS / 128, HH, BB);
    flash_kernel<<<fgrid, dim3(256), FLASH_SMEM>>>(qh, ql, kh, kl, vh, vl, ah, al);

    // 4) output projection (launch 7)
    gemm_bf16_kernel<true><<<ggrid, gblk, GEMM_SMEM>>>(
        ah, al, woh, wol, bo, 1.0f, nullptr, nullptr, out);
}